// round 1
// baseline (speedup 1.0000x reference)
#include <cuda_runtime.h>
#include <math.h>

#define NB   4      // batch
#define NV   4096   // vertices
#define NK   128    // eigenbasis
#define NCIN 16
#define NC   128    // width
#define NMLP 384    // 3*NC
#define NBLK 4

// Scratch (device globals; no allocation anywhere)
__device__ float g_f  [NB*NV*NMLP];  // packed [x | x_diff | gfeat]
__device__ float g_GXE[NB*NV*NK];    // gradX @ evecs (precomputed once)
__device__ float g_GYE[NB*NV*NK];    // gradY @ evecs
__device__ float g_s  [NB*NK*NC];    // coefs * x_spec
__device__ float g_gx [NB*NV*NC];
__device__ float g_gy [NB*NV*NC];
__device__ float g_h0 [NB*NV*NC];
__device__ float g_h1 [NB*NV*NC];

// ---------------------------------------------------------------------------
// Generic GEMM: C[M,128] = act(A[M,Kd] @ W[Kd,128] + bias [+ C]), batched.
// Block tile 64x128, 256 threads, per-thread 8x4. BK=16.
// ---------------------------------------------------------------------------
__global__ __launch_bounds__(256) void gemm_n128(
    const float* __restrict__ A, int ldA, long long sA,
    const float* __restrict__ W, long long sW,
    const float* __restrict__ bias,
    float* __restrict__ C, int ldC, long long sC,
    int Kd, int relu, int beta)
{
    __shared__ float As[16][68];
    __shared__ float Ws[16][128];

    const int bt = blockIdx.y;
    A += (long long)bt * sA;
    W += (long long)bt * sW;
    C += (long long)bt * sC;

    const int row0 = blockIdx.x * 64;
    const int tid  = threadIdx.x;

    const int am  = tid >> 2;          // 0..63 : A-tile row
    const int ak4 = (tid & 3) * 4;     // 0,4,8,12 : A-tile k (float4)
    const int tx  = tid & 31;
    const int ty  = tid >> 5;
    const int c0  = tx * 4;            // output cols
    const int r0  = ty * 8;            // output rows (within tile)

    float acc[8][4];
#pragma unroll
    for (int i = 0; i < 8; i++)
#pragma unroll
        for (int j = 0; j < 4; j++) acc[i][j] = 0.f;

    for (int k0 = 0; k0 < Kd; k0 += 16) {
        // stage global -> regs
        float4 av = *reinterpret_cast<const float4*>(
            &A[(long long)(row0 + am) * ldA + k0 + ak4]);
        const int i0 = tid * 2, i1 = i0 + 1;
        float4 wv0 = *reinterpret_cast<const float4*>(
            &W[(long long)(k0 + (i0 >> 5)) * 128 + (i0 & 31) * 4]);
        float4 wv1 = *reinterpret_cast<const float4*>(
            &W[(long long)(k0 + (i1 >> 5)) * 128 + (i1 & 31) * 4]);

        __syncthreads();
        As[ak4 + 0][am] = av.x;
        As[ak4 + 1][am] = av.y;
        As[ak4 + 2][am] = av.z;
        As[ak4 + 3][am] = av.w;
        *reinterpret_cast<float4*>(&Ws[i0 >> 5][(i0 & 31) * 4]) = wv0;
        *reinterpret_cast<float4*>(&Ws[i1 >> 5][(i1 & 31) * 4]) = wv1;
        __syncthreads();

#pragma unroll
        for (int kk = 0; kk < 16; kk++) {
            float4 w = *reinterpret_cast<const float4*>(&Ws[kk][c0]);
            float a[8];
#pragma unroll
            for (int i = 0; i < 8; i++) a[i] = As[kk][r0 + i];
#pragma unroll
            for (int i = 0; i < 8; i++) {
                acc[i][0] = fmaf(a[i], w.x, acc[i][0]);
                acc[i][1] = fmaf(a[i], w.y, acc[i][1]);
                acc[i][2] = fmaf(a[i], w.z, acc[i][2]);
                acc[i][3] = fmaf(a[i], w.w, acc[i][3]);
            }
        }
    }

    float4 bv = make_float4(0.f, 0.f, 0.f, 0.f);
    if (bias) bv = *reinterpret_cast<const float4*>(&bias[c0]);

#pragma unroll
    for (int i = 0; i < 8; i++) {
        long long off = (long long)(row0 + r0 + i) * ldC + c0;
        float4 r;
        r.x = acc[i][0] + bv.x;
        r.y = acc[i][1] + bv.y;
        r.z = acc[i][2] + bv.z;
        r.w = acc[i][3] + bv.w;
        if (beta) {
            float4 p = *reinterpret_cast<const float4*>(&C[off]);
            r.x += p.x; r.y += p.y; r.z += p.z; r.w += p.w;
        }
        if (relu) {
            r.x = fmaxf(r.x, 0.f); r.y = fmaxf(r.y, 0.f);
            r.z = fmaxf(r.z, 0.f); r.w = fmaxf(r.w, 0.f);
        }
        *reinterpret_cast<float4*>(&C[off]) = r;
    }
}

// ---------------------------------------------------------------------------
// Spectral: s[b,k,c] = exp(-evals[b,k]*max(t_i[c],1e-8)) *
//                      sum_v evecs[b,v,k] * x[b,v,c] * mass[b,v]
// grid (8,8,NB), 256 threads; 16x16 output tile, V tiled by 32.
// ---------------------------------------------------------------------------
__global__ __launch_bounds__(256) void spec_kernel(
    const float* __restrict__ evecs, const float* __restrict__ xf,
    const float* __restrict__ mass, const float* __restrict__ evals,
    const float* __restrict__ t_i, float* __restrict__ s)
{
    const int b  = blockIdx.z;
    const int k0 = blockIdx.x * 16;
    const int c0 = blockIdx.y * 16;
    const int tid = threadIdx.x;
    const int kk = tid >> 4;
    const int cc = tid & 15;

    __shared__ float E[32][17], X[32][17];

    const float* ev = evecs + (long long)b * NV * NK;
    const float* xb = xf + (long long)b * NV * NMLP;
    const float* mb = mass + b * NV;

    const int vl = tid >> 3;          // 0..31
    const int cl = (tid & 7) * 2;     // 0,2,...,14

    float acc = 0.f;
    for (int v0 = 0; v0 < NV; v0 += 32) {
        float2 e2 = *reinterpret_cast<const float2*>(
            &ev[(long long)(v0 + vl) * NK + k0 + cl]);
        float mm = mb[v0 + vl];
        float2 x2 = *reinterpret_cast<const float2*>(
            &xb[(long long)(v0 + vl) * NMLP + c0 + cl]);
        E[vl][cl]     = e2.x;
        E[vl][cl + 1] = e2.y;
        X[vl][cl]     = x2.x * mm;
        X[vl][cl + 1] = x2.y * mm;
        __syncthreads();
#pragma unroll
        for (int v = 0; v < 32; v++) acc = fmaf(E[v][kk], X[v][cc], acc);
        __syncthreads();
    }

    float ti = fmaxf(t_i[c0 + cc], 1e-8f);
    float coef = expf(-evals[b * NK + k0 + kk] * ti);
    s[((long long)b * NK + k0 + kk) * NC + c0 + cc] = coef * acc;
}

// ---------------------------------------------------------------------------
// Complex-linear + tanh fused:
//   br = gx@Are - gy@Aim ; bi = gy@Are + gx@Aim
//   gfeat = tanh(gx*br + gy*bi)  -> written to f cols [256:384]
// grid (NV/32, NB), 256 threads; tile 32x128, per-thread 4x4 (x2 accums).
// ---------------------------------------------------------------------------
__global__ __launch_bounds__(256) void complex_kernel(
    const float* __restrict__ gx, const float* __restrict__ gy,
    const float* __restrict__ Are, const float* __restrict__ Aim,
    float* __restrict__ f)
{
    const int b = blockIdx.y;
    const int row0 = blockIdx.x * 32;
    const float* gxb = gx + (long long)b * NV * NC;
    const float* gyb = gy + (long long)b * NV * NC;

    __shared__ float A1[16][36], A2[16][36];
    __shared__ float W1[16][128], W2[16][128];

    const int tid = threadIdx.x;
    const int tx = tid & 31, ty = tid >> 5;
    const int c0 = tx * 4, r0 = ty * 4;

    float br[4][4], bi[4][4];
#pragma unroll
    for (int i = 0; i < 4; i++)
#pragma unroll
        for (int j = 0; j < 4; j++) { br[i][j] = 0.f; bi[i][j] = 0.f; }

    const int vl = tid >> 3;        // 0..31
    const int kl = (tid & 7) * 2;   // 0..14

    for (int k0 = 0; k0 < NC; k0 += 16) {
        float2 a1 = *reinterpret_cast<const float2*>(
            &gxb[(long long)(row0 + vl) * NC + k0 + kl]);
        float2 a2 = *reinterpret_cast<const float2*>(
            &gyb[(long long)(row0 + vl) * NC + k0 + kl]);
        const int i0 = tid * 2, i1 = i0 + 1;
        float4 w10 = *reinterpret_cast<const float4*>(
            &Are[(long long)(k0 + (i0 >> 5)) * 128 + (i0 & 31) * 4]);
        float4 w11 = *reinterpret_cast<const float4*>(
            &Are[(long long)(k0 + (i1 >> 5)) * 128 + (i1 & 31) * 4]);
        float4 w20 = *reinterpret_cast<const float4*>(
            &Aim[(long long)(k0 + (i0 >> 5)) * 128 + (i0 & 31) * 4]);
        float4 w21 = *reinterpret_cast<const float4*>(
            &Aim[(long long)(k0 + (i1 >> 5)) * 128 + (i1 & 31) * 4]);

        __syncthreads();
        A1[kl][vl] = a1.x; A1[kl + 1][vl] = a1.y;
        A2[kl][vl] = a2.x; A2[kl + 1][vl] = a2.y;
        *reinterpret_cast<float4*>(&W1[i0 >> 5][(i0 & 31) * 4]) = w10;
        *reinterpret_cast<float4*>(&W1[i1 >> 5][(i1 & 31) * 4]) = w11;
        *reinterpret_cast<float4*>(&W2[i0 >> 5][(i0 & 31) * 4]) = w20;
        *reinterpret_cast<float4*>(&W2[i1 >> 5][(i1 & 31) * 4]) = w21;
        __syncthreads();

#pragma unroll
        for (int kk = 0; kk < 16; kk++) {
            float4 w1 = *reinterpret_cast<const float4*>(&W1[kk][c0]);
            float4 w2 = *reinterpret_cast<const float4*>(&W2[kk][c0]);
            float a1v[4], a2v[4];
#pragma unroll
            for (int i = 0; i < 4; i++) {
                a1v[i] = A1[kk][r0 + i];
                a2v[i] = A2[kk][r0 + i];
            }
#pragma unroll
            for (int i = 0; i < 4; i++) {
                br[i][0] = fmaf(a1v[i], w1.x, br[i][0]); br[i][0] = fmaf(-a2v[i], w2.x, br[i][0]);
                br[i][1] = fmaf(a1v[i], w1.y, br[i][1]); br[i][1] = fmaf(-a2v[i], w2.y, br[i][1]);
                br[i][2] = fmaf(a1v[i], w1.z, br[i][2]); br[i][2] = fmaf(-a2v[i], w2.z, br[i][2]);
                br[i][3] = fmaf(a1v[i], w1.w, br[i][3]); br[i][3] = fmaf(-a2v[i], w2.w, br[i][3]);
                bi[i][0] = fmaf(a2v[i], w1.x, bi[i][0]); bi[i][0] = fmaf(a1v[i], w2.x, bi[i][0]);
                bi[i][1] = fmaf(a2v[i], w1.y, bi[i][1]); bi[i][1] = fmaf(a1v[i], w2.y, bi[i][1]);
                bi[i][2] = fmaf(a2v[i], w1.z, bi[i][2]); bi[i][2] = fmaf(a1v[i], w2.z, bi[i][2]);
                bi[i][3] = fmaf(a2v[i], w1.w, bi[i][3]); bi[i][3] = fmaf(a1v[i], w2.w, bi[i][3]);
            }
        }
    }

#pragma unroll
    for (int i = 0; i < 4; i++) {
        const int row = row0 + r0 + i;
        float4 gxv = *reinterpret_cast<const float4*>(&gxb[(long long)row * NC + c0]);
        float4 gyv = *reinterpret_cast<const float4*>(&gyb[(long long)row * NC + c0]);
        float4 o;
        o.x = tanhf(gxv.x * br[i][0] + gyv.x * bi[i][0]);
        o.y = tanhf(gxv.y * br[i][1] + gyv.y * bi[i][1]);
        o.z = tanhf(gxv.z * br[i][2] + gyv.z * bi[i][2]);
        o.w = tanhf(gxv.w * br[i][3] + gyv.w * bi[i][3]);
        *reinterpret_cast<float4*>(
            &f[((long long)b * NV + row) * NMLP + 256 + c0]) = o;
    }
}

// ---------------------------------------------------------------------------
extern "C" void kernel_launch(void* const* d_in, const int* in_sizes, int n_in,
                              void* d_out, int out_size)
{
    const float* x_in  = (const float*)d_in[0];
    const float* mass  = (const float*)d_in[1];
    const float* evals = (const float*)d_in[2];
    const float* evecs = (const float*)d_in[3];
    const float* gradX = (const float*)d_in[4];
    const float* gradY = (const float*)d_in[5];
    const float* Wf    = (const float*)d_in[6];
    const float* bf    = (const float*)d_in[7];
    const float* Wl    = (const float*)d_in[8];
    const float* bl    = (const float*)d_in[9];
    const float* t     = (const float*)d_in[10];
    const float* Are   = (const float*)d_in[11];
    const float* Aim   = (const float*)d_in[12];
    const float* W0    = (const float*)d_in[13];
    const float* b0    = (const float*)d_in[14];
    const float* W1    = (const float*)d_in[15];
    const float* b1    = (const float*)d_in[16];
    const float* W2    = (const float*)d_in[17];
    const float* b2    = (const float*)d_in[18];
    float* out = (float*)d_out;

    float *f, *GXE, *GYE, *s, *gx, *gy, *h0, *h1;
    cudaGetSymbolAddress((void**)&f,   g_f);
    cudaGetSymbolAddress((void**)&GXE, g_GXE);
    cudaGetSymbolAddress((void**)&GYE, g_GYE);
    cudaGetSymbolAddress((void**)&s,   g_s);
    cudaGetSymbolAddress((void**)&gx,  g_gx);
    cudaGetSymbolAddress((void**)&gy,  g_gy);
    cudaGetSymbolAddress((void**)&h0,  g_h0);
    cudaGetSymbolAddress((void**)&h1,  g_h1);

    const long long sVK = (long long)NV * NK;
    const long long sVC = (long long)NV * NC;
    const long long sVM = (long long)NV * NMLP;
    const long long sKC = (long long)NK * NC;

    // x = x_in @ Wf + bf  -> f[:, 0:128]
    gemm_n128<<<dim3(NB * NV / 64, 1), 256>>>(
        x_in, NCIN, 0, Wf, 0, bf, f, NMLP, 0, NCIN, 0, 0);

    // Precompute GXE = gradX @ evecs, GYE = gradY @ evecs (block-invariant)
    gemm_n128<<<dim3(NV / 64, NB), 256>>>(
        gradX, NV, (long long)NV * NV, evecs, sVK, nullptr,
        GXE, NK, sVK, NV, 0, 0);
    gemm_n128<<<dim3(NV / 64, NB), 256>>>(
        gradY, NV, (long long)NV * NV, evecs, sVK, nullptr,
        GYE, NK, sVK, NV, 0, 0);

    for (int i = 0; i < NBLK; i++) {
        // s = exp(-evals*t_i) * (evecs^T @ (x*mass))
        spec_kernel<<<dim3(8, 8, NB), 256>>>(evecs, f, mass, evals,
                                             t + i * NC, s);
        // x_diff = evecs @ s  -> f[:, 128:256]
        gemm_n128<<<dim3(NV / 64, NB), 256>>>(
            evecs, NK, sVK, s, sKC, nullptr, f + NC, NMLP, sVM, NK, 0, 0);
        // gx = GXE @ s ; gy = GYE @ s
        gemm_n128<<<dim3(NV / 64, NB), 256>>>(
            GXE, NK, sVK, s, sKC, nullptr, gx, NC, sVC, NK, 0, 0);
        gemm_n128<<<dim3(NV / 64, NB), 256>>>(
            GYE, NK, sVK, s, sKC, nullptr, gy, NC, sVC, NK, 0, 0);
        // gfeat -> f[:, 256:384]
        complex_kernel<<<dim3(NV / 32, NB), 256>>>(
            gx, gy, Are + (long long)i * NC * NC,
            Aim + (long long)i * NC * NC, f);
        // MLP
        gemm_n128<<<dim3(NB * NV / 64, 1), 256>>>(
            f, NMLP, 0, W0 + (long long)i * NMLP * NC, 0, b0 + i * NC,
            h0, NC, 0, NMLP, 1, 0);
        gemm_n128<<<dim3(NB * NV / 64, 1), 256>>>(
            h0, NC, 0, W1 + (long long)i * NC * NC, 0, b1 + i * NC,
            h1, NC, 0, NC, 1, 0);
        // x += h1 @ W2 + b2  (beta=1, into f[:, 0:128])
        gemm_n128<<<dim3(NB * NV / 64, 1), 256>>>(
            h1, NC, 0, W2 + (long long)i * NC * NC, 0, b2 + i * NC,
            f, NMLP, 0, NC, 0, 1);
    }

    // out = x @ Wl + bl
    gemm_n128<<<dim3(NB * NV / 64, 1), 256>>>(
        f, NMLP, 0, Wl, 0, bl, out, NC, 0, NC, 0, 0);
}

// round 3
// speedup vs baseline: 1.6327x; 1.6327x over previous
#include <cuda_runtime.h>
#include <cuda_bf16.h>
#include <math.h>
#include <cstdint>

#define NB   4      // batch
#define NV   4096   // vertices
#define NK   128    // eigenbasis
#define NCIN 16
#define NC   128    // width
#define NMLP 384    // 3*NC
#define NBLK 4
#define NSLICE 32   // split-K slices for spectral projection

// ---------------------------------------------------------------------------
// Scratch (device globals; no allocation anywhere)
// ---------------------------------------------------------------------------
__device__ float g_f  [NB*NV*NMLP];  // packed [x | x_diff | gfeat]
__device__ float g_GXE[NB*NV*NK];    // gradX @ evecs (precomputed once)
__device__ float g_GYE[NB*NV*NK];    // gradY @ evecs
__device__ float g_s  [NB*NK*NC];    // coefs * x_spec
__device__ float g_gx [NB*NV*NC];
__device__ float g_gy [NB*NV*NC];
__device__ float g_h0 [NB*NV*NC];
__device__ float g_h1 [NB*NV*NC];
__device__ float g_P  [NB*NSLICE*NK*NC];          // spec split-K partials
__device__ __nv_bfloat16 g_evTh[NB*NK*NV];        // evecs^T hi (bf16, K-major)
__device__ __nv_bfloat16 g_evTl[NB*NK*NV];        // evecs^T lo

// ---------------------------------------------------------------------------
// helpers
// ---------------------------------------------------------------------------
__device__ __forceinline__ uint32_t smem_to_u32(const void* smem_ptr) {
    uint32_t addr;
    asm("{ .reg .u64 tmp; cvta.to.shared.u64 tmp, %1; cvt.u32.u64 %0, tmp; }"
        : "=r"(addr) : "l"(smem_ptr));
    return addr;
}

#define SWZ(o) ((o) ^ (((o) >> 3) & 0x70))

__device__ __forceinline__ void ldm4(uint32_t* r, uint32_t addr) {
    asm volatile("ldmatrix.sync.aligned.m8n8.x4.shared.b16 {%0,%1,%2,%3}, [%4];"
        : "=r"(r[0]), "=r"(r[1]), "=r"(r[2]), "=r"(r[3]) : "r"(addr));
}

__device__ __forceinline__ void mma16816(float* d, const uint32_t* a, const uint32_t* b) {
    asm volatile(
        "mma.sync.aligned.m16n8k16.row.col.f32.bf16.bf16.f32 "
        "{%0,%1,%2,%3}, {%4,%5,%6,%7}, {%8,%9}, {%0,%1,%2,%3};"
        : "+f"(d[0]), "+f"(d[1]), "+f"(d[2]), "+f"(d[3])
        : "r"(a[0]), "r"(a[1]), "r"(a[2]), "r"(a[3]), "r"(b[0]), "r"(b[1]));
}

__device__ __forceinline__ unsigned short bfbits(__nv_bfloat16 h) {
    return *reinterpret_cast<unsigned short*>(&h);
}

// ---------------------------------------------------------------------------
// evecs [b][v][k] fp32  ->  evT hi/lo bf16 [b][k][v]  (transpose + split)
// grid (NV/32, NK/32, NB), block (32,8)
// ---------------------------------------------------------------------------
__global__ void ev_split(const float* __restrict__ evecs,
                         __nv_bfloat16* __restrict__ eh,
                         __nv_bfloat16* __restrict__ el)
{
    __shared__ float tile[32][33];
    const int b = blockIdx.z;
    const int v0 = blockIdx.x * 32;
    const int k0 = blockIdx.y * 32;
    const int tx = threadIdx.x, ty = threadIdx.y;
    const float* src = evecs + ((long long)b * NV + v0) * NK + k0;
#pragma unroll
    for (int j = 0; j < 32; j += 8)
        tile[ty + j][tx] = src[(long long)(ty + j) * NK + tx];
    __syncthreads();
#pragma unroll
    for (int j = 0; j < 32; j += 8) {
        float x = tile[tx][ty + j];
        __nv_bfloat16 h = __float2bfloat16(x);
        __nv_bfloat16 l = __float2bfloat16(x - __bfloat162float(h));
        long long o = ((long long)b * NK + k0 + ty + j) * NV + v0 + tx;
        eh[o] = h;
        el[o] = l;
    }
}

// ---------------------------------------------------------------------------
// mma.sync GEMM: C[b,m,n] = sum_v A[b,m,v] * evecs[b,v,n]
//   A = gradX or gradY (fp32, split to bf16 hi/lo on the fly)
//   B = evT hi/lo bf16 [b][n][v] (K-major)
// bf16x3 emulation: Ah*Bh + Ah*Bl + Al*Bh. Tile M=128, N=128, kchunk=64.
// grid (NV/128, NB, 2), 256 threads (8 warps, each 32x64), 64 KB dyn smem.
// ---------------------------------------------------------------------------
#define SM_MM_TOTAL 65536

__global__ __launch_bounds__(256) void mm_mma(
    const float* __restrict__ gradX, const float* __restrict__ gradY,
    const __nv_bfloat16* __restrict__ evTh, const __nv_bfloat16* __restrict__ evTl,
    float* __restrict__ GXE, float* __restrict__ GYE)
{
    extern __shared__ char smem[];
    char* sAh = smem;
    char* sAl = smem + 16384;
    const uint32_t base = smem_to_u32(smem);
    const uint32_t uAh = base, uAl = base + 16384;
    const uint32_t uBh = base + 32768, uBl = base + 49152;

    const int tid  = threadIdx.x;
    const int wid  = tid >> 5;
    const int lane = tid & 31;

    const int b    = blockIdx.y;
    const int row0 = blockIdx.x * 128;
    const int mat  = blockIdx.z;

    const float* Abase = (mat ? gradY : gradX)
                         + (long long)b * NV * NV + (long long)row0 * NV;
    const __nv_bfloat16* Bh = evTh + (long long)b * NK * NV;
    const __nv_bfloat16* Bl = evTl + (long long)b * NK * NV;
    float* C = (mat ? GYE : GXE) + (long long)b * NV * NK + (long long)row0 * NK;

    const int wr  = wid & 3;       // warp row group (32 rows)
    const int wc  = wid >> 2;      // warp col group (64 cols)
    const int rw0 = wr * 32;
    const int cw0 = wc * 64;

    const int grp = lane >> 3;     // ldmatrix address group
    const int lr  = lane & 7;

    float acc[2][8][4];
#pragma unroll
    for (int mi = 0; mi < 2; mi++)
#pragma unroll
        for (int ni = 0; ni < 8; ni++)
#pragma unroll
            for (int q = 0; q < 4; q++) acc[mi][ni][q] = 0.f;

    for (int k0 = 0; k0 < NV; k0 += 64) {
        __syncthreads();   // all warps done reading smem from prev chunk

        // ---- B tiles via cp.async (straight bf16 copies, swizzled dst) ----
#pragma unroll
        for (int g = 0; g < 4; g++) {
            const int G   = tid + 256 * g;
            const int row = G >> 3;
            const int v8  = (G & 7) * 8;
            const uint32_t sw = SWZ((uint32_t)(row * 128 + v8 * 2));
            const void* srch = Bh + (long long)row * NV + k0 + v8;
            const void* srcl = Bl + (long long)row * NV + k0 + v8;
            asm volatile("cp.async.cg.shared.global [%0], [%1], 16;"
                         :: "r"(uBh + sw), "l"(srch));
            asm volatile("cp.async.cg.shared.global [%0], [%1], 16;"
                         :: "r"(uBl + sw), "l"(srcl));
        }
        asm volatile("cp.async.commit_group;" ::: "memory");

        // ---- A tiles: fp32 -> bf16 hi/lo split, swizzled stores ----
#pragma unroll
        for (int g = 0; g < 4; g++) {
            const int G   = tid + 256 * g;
            const int row = G >> 3;
            const int v8  = (G & 7) * 8;
            const float* ap = Abase + (long long)row * NV + k0 + v8;
            float4 f0 = *reinterpret_cast<const float4*>(ap);
            float4 f1 = *reinterpret_cast<const float4*>(ap + 4);
            float xs[8] = {f0.x, f0.y, f0.z, f0.w, f1.x, f1.y, f1.z, f1.w};
            unsigned int hw[4], lw[4];
#pragma unroll
            for (int e = 0; e < 4; e++) {
                __nv_bfloat16 h0 = __float2bfloat16(xs[2*e]);
                __nv_bfloat16 h1 = __float2bfloat16(xs[2*e+1]);
                __nv_bfloat16 l0 = __float2bfloat16(xs[2*e]   - __bfloat162float(h0));
                __nv_bfloat16 l1 = __float2bfloat16(xs[2*e+1] - __bfloat162float(h1));
                hw[e] = (unsigned)bfbits(h0) | ((unsigned)bfbits(h1) << 16);
                lw[e] = (unsigned)bfbits(l0) | ((unsigned)bfbits(l1) << 16);
            }
            const uint32_t sw = SWZ((uint32_t)(row * 128 + v8 * 2));
            *reinterpret_cast<uint4*>(sAh + sw) = make_uint4(hw[0], hw[1], hw[2], hw[3]);
            *reinterpret_cast<uint4*>(sAl + sw) = make_uint4(lw[0], lw[1], lw[2], lw[3]);
        }
        asm volatile("cp.async.wait_group 0;" ::: "memory");
        __syncthreads();

        // ---- compute: 4 k16 steps x 3 terms ----
#pragma unroll
        for (int ks = 0; ks < 64; ks += 16) {
            uint32_t offA[2], offB[4];
#pragma unroll
            for (int mi = 0; mi < 2; mi++) {
                const int ar = rw0 + mi * 16 + (grp & 1) * 8 + lr;
                const int ac = ks + (grp >> 1) * 8;
                offA[mi] = SWZ((uint32_t)(ar * 128 + ac * 2));
            }
#pragma unroll
            for (int nb = 0; nb < 4; nb++) {
                const int br = cw0 + nb * 16 + (grp >> 1) * 8 + lr;
                const int bc = ks + (grp & 1) * 8;
                offB[nb] = SWZ((uint32_t)(br * 128 + bc * 2));
            }
#pragma unroll
            for (int t = 0; t < 3; t++) {
                const uint32_t ab = (t == 2) ? uAl : uAh;
                const uint32_t bb = (t == 1) ? uBl : uBh;
                uint32_t afr[2][4], bfr[4][4];
#pragma unroll
                for (int mi = 0; mi < 2; mi++) ldm4(afr[mi], ab + offA[mi]);
#pragma unroll
                for (int nb = 0; nb < 4; nb++) ldm4(bfr[nb], bb + offB[nb]);
#pragma unroll
                for (int mi = 0; mi < 2; mi++)
#pragma unroll
                    for (int ni = 0; ni < 8; ni++)
                        mma16816(acc[mi][ni], afr[mi], &bfr[ni >> 1][(ni & 1) * 2]);
            }
        }
    }

    // ---- epilogue: registers -> C ----
    const int orow  = lane >> 2;
    const int ocol2 = (lane & 3) * 2;
#pragma unroll
    for (int mi = 0; mi < 2; mi++)
#pragma unroll
        for (int ni = 0; ni < 8; ni++) {
            const int r = rw0 + mi * 16 + orow;
            const int c = cw0 + ni * 8 + ocol2;
            *reinterpret_cast<float2*>(&C[(long long)r * NK + c]) =
                make_float2(acc[mi][ni][0], acc[mi][ni][1]);
            *reinterpret_cast<float2*>(&C[(long long)(r + 8) * NK + c]) =
                make_float2(acc[mi][ni][2], acc[mi][ni][3]);
        }
}

// ---------------------------------------------------------------------------
// Generic GEMM: C[M,128] = act(A[M,Kd] @ W[Kd,128] + bias [+ C]), batched.
// Block tile 64x128, 256 threads, per-thread 8x4. BK=16.
// ---------------------------------------------------------------------------
__global__ __launch_bounds__(256) void gemm_n128(
    const float* __restrict__ A, int ldA, long long sA,
    const float* __restrict__ W, long long sW,
    const float* __restrict__ bias,
    float* __restrict__ C, int ldC, long long sC,
    int Kd, int relu, int beta)
{
    __shared__ float As[16][68];
    __shared__ float Ws[16][128];

    const int bt = blockIdx.y;
    A += (long long)bt * sA;
    W += (long long)bt * sW;
    C += (long long)bt * sC;

    const int row0 = blockIdx.x * 64;
    const int tid  = threadIdx.x;

    const int am  = tid >> 2;
    const int ak4 = (tid & 3) * 4;
    const int tx  = tid & 31;
    const int ty  = tid >> 5;
    const int c0  = tx * 4;
    const int r0  = ty * 8;

    float acc[8][4];
#pragma unroll
    for (int i = 0; i < 8; i++)
#pragma unroll
        for (int j = 0; j < 4; j++) acc[i][j] = 0.f;

    for (int k0 = 0; k0 < Kd; k0 += 16) {
        float4 av = *reinterpret_cast<const float4*>(
            &A[(long long)(row0 + am) * ldA + k0 + ak4]);
        const int i0 = tid * 2, i1 = i0 + 1;
        float4 wv0 = *reinterpret_cast<const float4*>(
            &W[(long long)(k0 + (i0 >> 5)) * 128 + (i0 & 31) * 4]);
        float4 wv1 = *reinterpret_cast<const float4*>(
            &W[(long long)(k0 + (i1 >> 5)) * 128 + (i1 & 31) * 4]);

        __syncthreads();
        As[ak4 + 0][am] = av.x;
        As[ak4 + 1][am] = av.y;
        As[ak4 + 2][am] = av.z;
        As[ak4 + 3][am] = av.w;
        *reinterpret_cast<float4*>(&Ws[i0 >> 5][(i0 & 31) * 4]) = wv0;
        *reinterpret_cast<float4*>(&Ws[i1 >> 5][(i1 & 31) * 4]) = wv1;
        __syncthreads();

#pragma unroll
        for (int kk = 0; kk < 16; kk++) {
            float4 w = *reinterpret_cast<const float4*>(&Ws[kk][c0]);
            float a[8];
#pragma unroll
            for (int i = 0; i < 8; i++) a[i] = As[kk][r0 + i];
#pragma unroll
            for (int i = 0; i < 8; i++) {
                acc[i][0] = fmaf(a[i], w.x, acc[i][0]);
                acc[i][1] = fmaf(a[i], w.y, acc[i][1]);
                acc[i][2] = fmaf(a[i], w.z, acc[i][2]);
                acc[i][3] = fmaf(a[i], w.w, acc[i][3]);
            }
        }
    }

    float4 bv = make_float4(0.f, 0.f, 0.f, 0.f);
    if (bias) bv = *reinterpret_cast<const float4*>(&bias[c0]);

#pragma unroll
    for (int i = 0; i < 8; i++) {
        long long off = (long long)(row0 + r0 + i) * ldC + c0;
        float4 r;
        r.x = acc[i][0] + bv.x;
        r.y = acc[i][1] + bv.y;
        r.z = acc[i][2] + bv.z;
        r.w = acc[i][3] + bv.w;
        if (beta) {
            float4 p = *reinterpret_cast<const float4*>(&C[off]);
            r.x += p.x; r.y += p.y; r.z += p.z; r.w += p.w;
        }
        if (relu) {
            r.x = fmaxf(r.x, 0.f); r.y = fmaxf(r.y, 0.f);
            r.z = fmaxf(r.z, 0.f); r.w = fmaxf(r.w, 0.f);
        }
        *reinterpret_cast<float4*>(&C[off]) = r;
    }
}

// ---------------------------------------------------------------------------
// Spectral projection, split-K stage 1:
//   P[b,sl,k,c] = sum_{v in slice} evecs[b,v,k] * x[b,v,c] * mass[b,v]
// grid (NSLICE, NB), 256 threads; 128x128 out tile, 8x8 microtile.
// ---------------------------------------------------------------------------
__global__ __launch_bounds__(256) void spec1(
    const float* __restrict__ evecs, const float* __restrict__ f,
    const float* __restrict__ mass, float* __restrict__ P)
{
    const int b  = blockIdx.y;
    const int sl = blockIdx.x;
    const int v0base = sl * (NV / NSLICE);   // 128 vertices per slice

    __shared__ float E[32][132], X[32][132];

    const float* ev = evecs + (long long)b * NV * NK;
    const float* xb = f + (long long)b * NV * NMLP;
    const float* mb = mass + b * NV;

    const int tid = threadIdx.x;
    const int vr = tid >> 3;            // 0..31
    const int cb = (tid & 7) * 16;      // 0..112
    const int r0 = (tid >> 4) * 8;      // k-tile base
    const int c0 = (tid & 15) * 8;      // c-tile base

    float acc[8][8];
#pragma unroll
    for (int i = 0; i < 8; i++)
#pragma unroll
        for (int j = 0; j < 8; j++) acc[i][j] = 0.f;

    for (int v0 = v0base; v0 < v0base + NV / NSLICE; v0 += 32) {
        const float* er = &ev[(long long)(v0 + vr) * NK + cb];
        const float* xr = &xb[(long long)(v0 + vr) * NMLP + cb];
        const float m = mb[v0 + vr];
        float4 e0 = *reinterpret_cast<const float4*>(er + 0);
        float4 e1 = *reinterpret_cast<const float4*>(er + 4);
        float4 e2 = *reinterpret_cast<const float4*>(er + 8);
        float4 e3 = *reinterpret_cast<const float4*>(er + 12);
        float4 x0 = *reinterpret_cast<const float4*>(xr + 0);
        float4 x1 = *reinterpret_cast<const float4*>(xr + 4);
        float4 x2 = *reinterpret_cast<const float4*>(xr + 8);
        float4 x3 = *reinterpret_cast<const float4*>(xr + 12);
        __syncthreads();
        *reinterpret_cast<float4*>(&E[vr][cb + 0])  = e0;
        *reinterpret_cast<float4*>(&E[vr][cb + 4])  = e1;
        *reinterpret_cast<float4*>(&E[vr][cb + 8])  = e2;
        *reinterpret_cast<float4*>(&E[vr][cb + 12]) = e3;
        x0.x *= m; x0.y *= m; x0.z *= m; x0.w *= m;
        x1.x *= m; x1.y *= m; x1.z *= m; x1.w *= m;
        x2.x *= m; x2.y *= m; x2.z *= m; x2.w *= m;
        x3.x *= m; x3.y *= m; x3.z *= m; x3.w *= m;
        *reinterpret_cast<float4*>(&X[vr][cb + 0])  = x0;
        *reinterpret_cast<float4*>(&X[vr][cb + 4])  = x1;
        *reinterpret_cast<float4*>(&X[vr][cb + 8])  = x2;
        *reinterpret_cast<float4*>(&X[vr][cb + 12]) = x3;
        __syncthreads();

#pragma unroll
        for (int v = 0; v < 32; v++) {
            float ka[8], xa[8];
            *reinterpret_cast<float4*>(ka)     = *reinterpret_cast<const float4*>(&E[v][r0]);
            *reinterpret_cast<float4*>(ka + 4) = *reinterpret_cast<const float4*>(&E[v][r0 + 4]);
            *reinterpret_cast<float4*>(xa)     = *reinterpret_cast<const float4*>(&X[v][c0]);
            *reinterpret_cast<float4*>(xa + 4) = *reinterpret_cast<const float4*>(&X[v][c0 + 4]);
#pragma unroll
            for (int i = 0; i < 8; i++)
#pragma unroll
                for (int j = 0; j < 8; j++)
                    acc[i][j] = fmaf(ka[i], xa[j], acc[i][j]);
        }
    }

#pragma unroll
    for (int i = 0; i < 8; i++) {
        float* pr = &P[(((long long)b * NSLICE + sl) * NK + r0 + i) * NC + c0];
        *reinterpret_cast<float4*>(pr)     = make_float4(acc[i][0], acc[i][1], acc[i][2], acc[i][3]);
        *reinterpret_cast<float4*>(pr + 4) = make_float4(acc[i][4], acc[i][5], acc[i][6], acc[i][7]);
    }
}

// ---------------------------------------------------------------------------
// Spectral stage 2: s[b,k,c] = exp(-evals[b,k]*max(t_i[c],1e-8)) * sum_sl P
// ---------------------------------------------------------------------------
__global__ __launch_bounds__(256) void spec2(
    const float* __restrict__ P, const float* __restrict__ evals,
    const float* __restrict__ t_i, float* __restrict__ s)
{
    const int idx = blockIdx.x * 256 + threadIdx.x;
    const int c = idx & (NC - 1);
    const int k = (idx >> 7) & (NK - 1);
    const int b = idx >> 14;
    float acc = 0.f;
#pragma unroll
    for (int sl = 0; sl < NSLICE; sl++)
        acc += P[(((long long)b * NSLICE + sl) * NK + k) * NC + c];
    const float ti = fmaxf(t_i[c], 1e-8f);
    s[idx] = expf(-evals[b * NK + k] * ti) * acc;
}

// ---------------------------------------------------------------------------
// Complex-linear + tanh fused
// ---------------------------------------------------------------------------
__global__ __launch_bounds__(256) void complex_kernel(
    const float* __restrict__ gx, const float* __restrict__ gy,
    const float* __restrict__ Are, const float* __restrict__ Aim,
    float* __restrict__ f)
{
    const int b = blockIdx.y;
    const int row0 = blockIdx.x * 32;
    const float* gxb = gx + (long long)b * NV * NC;
    const float* gyb = gy + (long long)b * NV * NC;

    __shared__ float A1[16][36], A2[16][36];
    __shared__ float W1[16][128], W2[16][128];

    const int tid = threadIdx.x;
    const int tx = tid & 31, ty = tid >> 5;
    const int c0 = tx * 4, r0 = ty * 4;

    float br[4][4], bi[4][4];
#pragma unroll
    for (int i = 0; i < 4; i++)
#pragma unroll
        for (int j = 0; j < 4; j++) { br[i][j] = 0.f; bi[i][j] = 0.f; }

    const int vl = tid >> 3;
    const int kl = (tid & 7) * 2;

    for (int k0 = 0; k0 < NC; k0 += 16) {
        float2 a1 = *reinterpret_cast<const float2*>(
            &gxb[(long long)(row0 + vl) * NC + k0 + kl]);
        float2 a2 = *reinterpret_cast<const float2*>(
            &gyb[(long long)(row0 + vl) * NC + k0 + kl]);
        const int i0 = tid * 2, i1 = i0 + 1;
        float4 w10 = *reinterpret_cast<const float4*>(
            &Are[(long long)(k0 + (i0 >> 5)) * 128 + (i0 & 31) * 4]);
        float4 w11 = *reinterpret_cast<const float4*>(
            &Are[(long long)(k0 + (i1 >> 5)) * 128 + (i1 & 31) * 4]);
        float4 w20 = *reinterpret_cast<const float4*>(
            &Aim[(long long)(k0 + (i0 >> 5)) * 128 + (i0 & 31) * 4]);
        float4 w21 = *reinterpret_cast<const float4*>(
            &Aim[(long long)(k0 + (i1 >> 5)) * 128 + (i1 & 31) * 4]);

        __syncthreads();
        A1[kl][vl] = a1.x; A1[kl + 1][vl] = a1.y;
        A2[kl][vl] = a2.x; A2[kl + 1][vl] = a2.y;
        *reinterpret_cast<float4*>(&W1[i0 >> 5][(i0 & 31) * 4]) = w10;
        *reinterpret_cast<float4*>(&W1[i1 >> 5][(i1 & 31) * 4]) = w11;
        *reinterpret_cast<float4*>(&W2[i0 >> 5][(i0 & 31) * 4]) = w20;
        *reinterpret_cast<float4*>(&W2[i1 >> 5][(i1 & 31) * 4]) = w21;
        __syncthreads();

#pragma unroll
        for (int kk = 0; kk < 16; kk++) {
            float4 w1 = *reinterpret_cast<const float4*>(&W1[kk][c0]);
            float4 w2 = *reinterpret_cast<const float4*>(&W2[kk][c0]);
            float a1v[4], a2v[4];
#pragma unroll
            for (int i = 0; i < 4; i++) {
                a1v[i] = A1[kk][r0 + i];
                a2v[i] = A2[kk][r0 + i];
            }
#pragma unroll
            for (int i = 0; i < 4; i++) {
                br[i][0] = fmaf(a1v[i], w1.x, br[i][0]); br[i][0] = fmaf(-a2v[i], w2.x, br[i][0]);
                br[i][1] = fmaf(a1v[i], w1.y, br[i][1]); br[i][1] = fmaf(-a2v[i], w2.y, br[i][1]);
                br[i][2] = fmaf(a1v[i], w1.z, br[i][2]); br[i][2] = fmaf(-a2v[i], w2.z, br[i][2]);
                br[i][3] = fmaf(a1v[i], w1.w, br[i][3]); br[i][3] = fmaf(-a2v[i], w2.w, br[i][3]);
                bi[i][0] = fmaf(a2v[i], w1.x, bi[i][0]); bi[i][0] = fmaf(a1v[i], w2.x, bi[i][0]);
                bi[i][1] = fmaf(a2v[i], w1.y, bi[i][1]); bi[i][1] = fmaf(a1v[i], w2.y, bi[i][1]);
                bi[i][2] = fmaf(a2v[i], w1.z, bi[i][2]); bi[i][2] = fmaf(a1v[i], w2.z, bi[i][2]);
                bi[i][3] = fmaf(a2v[i], w1.w, bi[i][3]); bi[i][3] = fmaf(a1v[i], w2.w, bi[i][3]);
            }
        }
    }

#pragma unroll
    for (int i = 0; i < 4; i++) {
        const int row = row0 + r0 + i;
        float4 gxv = *reinterpret_cast<const float4*>(&gxb[(long long)row * NC + c0]);
        float4 gyv = *reinterpret_cast<const float4*>(&gyb[(long long)row * NC + c0]);
        float4 o;
        o.x = tanhf(gxv.x * br[i][0] + gyv.x * bi[i][0]);
        o.y = tanhf(gxv.y * br[i][1] + gyv.y * bi[i][1]);
        o.z = tanhf(gxv.z * br[i][2] + gyv.z * bi[i][2]);
        o.w = tanhf(gxv.w * br[i][3] + gyv.w * bi[i][3]);
        *reinterpret_cast<float4*>(
            &f[((long long)b * NV + row) * NMLP + 256 + c0]) = o;
    }
}

// ---------------------------------------------------------------------------
extern "C" void kernel_launch(void* const* d_in, const int* in_sizes, int n_in,
                              void* d_out, int out_size)
{
    const float* x_in  = (const float*)d_in[0];
    const float* mass  = (const float*)d_in[1];
    const float* evals = (const float*)d_in[2];
    const float* evecs = (const float*)d_in[3];
    const float* gradX = (const float*)d_in[4];
    const float* gradY = (const float*)d_in[5];
    const float* Wf    = (const float*)d_in[6];
    const float* bf    = (const float*)d_in[7];
    const float* Wl    = (const float*)d_in[8];
    const float* bl    = (const float*)d_in[9];
    const float* t     = (const float*)d_in[10];
    const float* Are   = (const float*)d_in[11];
    const float* Aim   = (const float*)d_in[12];
    const float* W0    = (const float*)d_in[13];
    const float* b0    = (const float*)d_in[14];
    const float* W1    = (const float*)d_in[15];
    const float* b1    = (const float*)d_in[16];
    const float* W2    = (const float*)d_in[17];
    const float* b2    = (const float*)d_in[18];
    float* out = (float*)d_out;

    float *f, *GXE, *GYE, *s, *gx, *gy, *h0, *h1, *P;
    __nv_bfloat16 *evTh, *evTl;
    cudaGetSymbolAddress((void**)&f,    g_f);
    cudaGetSymbolAddress((void**)&GXE,  g_GXE);
    cudaGetSymbolAddress((void**)&GYE,  g_GYE);
    cudaGetSymbolAddress((void**)&s,    g_s);
    cudaGetSymbolAddress((void**)&gx,   g_gx);
    cudaGetSymbolAddress((void**)&gy,   g_gy);
    cudaGetSymbolAddress((void**)&h0,   g_h0);
    cudaGetSymbolAddress((void**)&h1,   g_h1);
    cudaGetSymbolAddress((void**)&P,    g_P);
    cudaGetSymbolAddress((void**)&evTh, g_evTh);
    cudaGetSymbolAddress((void**)&evTl, g_evTl);

    cudaFuncSetAttribute(mm_mma, cudaFuncAttributeMaxDynamicSharedMemorySize,
                         SM_MM_TOTAL);

    const long long sVK = (long long)NV * NK;
    const long long sVC = (long long)NV * NC;
    const long long sVM = (long long)NV * NMLP;
    const long long sKC = (long long)NK * NC;

    // x = x_in @ Wf + bf  -> f[:, 0:128]
    gemm_n128<<<dim3(NB * NV / 64, 1), 256>>>(
        x_in, NCIN, 0, Wf, 0, bf, f, NMLP, 0, NCIN, 0, 0);

    // evecs -> transposed bf16 hi/lo (B operand for tensor-core GEMM)
    ev_split<<<dim3(NV / 32, NK / 32, NB), dim3(32, 8)>>>(evecs, evTh, evTl);

    // GXE = gradX @ evecs, GYE = gradY @ evecs via mma.sync bf16x3
    mm_mma<<<dim3(NV / 128, NB, 2), 256, SM_MM_TOTAL>>>(
        gradX, gradY, evTh, evTl, GXE, GYE);

    for (int i = 0; i < NBLK; i++) {
        // s = exp(-evals*t_i) * (evecs^T @ (x*mass))  (split-K)
        spec1<<<dim3(NSLICE, NB), 256>>>(evecs, f, mass, P);
        spec2<<<dim3(NB * NK * NC / 256, 1), 256>>>(P, evals, t + i * NC, s);
        // x_diff = evecs @ s  -> f[:, 128:256]
        gemm_n128<<<dim3(NV / 64, NB), 256>>>(
            evecs, NK, sVK, s, sKC, nullptr, f + NC, NMLP, sVM, NK, 0, 0);
        // gx = GXE @ s ; gy = GYE @ s
        gemm_n128<<<dim3(NV / 64, NB), 256>>>(
            GXE, NK, sVK, s, sKC, nullptr, gx, NC, sVC, NK, 0, 0);
        gemm_n128<<<dim3(NV / 64, NB), 256>>>(
            GYE, NK, sVK, s, sKC, nullptr, gy, NC, sVC, NK, 0, 0);
        // gfeat -> f[:, 256:384]
        complex_kernel<<<dim3(NV / 32, NB), 256>>>(
            gx, gy, Are + (long long)i * NC * NC,
            Aim + (long long)i * NC * NC, f);
        // MLP
        gemm_n128<<<dim3(NB * NV / 64, 1), 256>>>(
            f, NMLP, 0, W0 + (long long)i * NMLP * NC, 0, b0 + i * NC,
            h0, NC, 0, NMLP, 1, 0);
        gemm_n128<<<dim3(NB * NV / 64, 1), 256>>>(
            h0, NC, 0, W1 + (long long)i * NC * NC, 0, b1 + i * NC,
            h1, NC, 0, NC, 1, 0);
        // x += h1 @ W2 + b2  (beta=1, into f[:, 0:128])
        gemm_n128<<<dim3(NB * NV / 64, 1), 256>>>(
            h1, NC, 0, W2 + (long long)i * NC * NC, 0, b2 + i * NC,
            f, NMLP, 0, NC, 0, 1);
    }

    // out = x @ Wl + bl
    gemm_n128<<<dim3(NB * NV / 64, 1), 256>>>(
        f, NMLP, 0, Wl, 0, bl, out, NC, 0, NC, 0, 0);
}

// round 5
// speedup vs baseline: 2.0898x; 1.2799x over previous
#include <cuda_runtime.h>
#include <cuda_bf16.h>
#include <math.h>
#include <cstdint>

#define NB   4      // batch
#define NV   4096   // vertices
#define NK   128    // eigenbasis
#define NCIN 16
#define NC   128    // width
#define NMLP 384    // 3*NC
#define NBLK 4
#define NSLICE 64   // split-K slices for spectral projection

// flags for gemm_mma
#define F_RELU   1
#define F_BETA   2
#define F_ASPLIT 4
#define F_OSPLIT 8

// ---------------------------------------------------------------------------
// Scratch (device globals; no allocation anywhere)
// ---------------------------------------------------------------------------
__device__ float g_f[NB*NV*NMLP];                 // packed [x | x_diff | gfeat]
__device__ float g_P[NB*NSLICE*NK*NC];            // spec split-K partials
__device__ __nv_bfloat16 g_evTh[NB*NK*NV];        // evecs^T hi (K-major, for mm_mma B)
__device__ __nv_bfloat16 g_evTl[NB*NK*NV];
__device__ __nv_bfloat16 g_evh [NB*NV*NK];        // evecs hi (row-major, A operand)
__device__ __nv_bfloat16 g_evl [NB*NV*NK];
__device__ __nv_bfloat16 g_GXEh[NB*NV*NK], g_GXEl[NB*NV*NK];
__device__ __nv_bfloat16 g_GYEh[NB*NV*NK], g_GYEl[NB*NV*NK];
__device__ __nv_bfloat16 g_sTh[NB*NC*NK], g_sTl[NB*NC*NK];   // s^T [c][k]
__device__ __nv_bfloat16 g_gxh[NB*NV*NC], g_gxl[NB*NV*NC];
__device__ __nv_bfloat16 g_gyh[NB*NV*NC], g_gyl[NB*NV*NC];
__device__ __nv_bfloat16 g_h0h[NB*NV*NC], g_h0l[NB*NV*NC];
__device__ __nv_bfloat16 g_h1h[NB*NV*NC], g_h1l[NB*NV*NC];
__device__ __nv_bfloat16 g_W0Th[NBLK*NC*NMLP], g_W0Tl[NBLK*NC*NMLP];
__device__ __nv_bfloat16 g_W1Th[NBLK*NC*NC],  g_W1Tl[NBLK*NC*NC];
__device__ __nv_bfloat16 g_W2Th[NBLK*NC*NC],  g_W2Tl[NBLK*NC*NC];
__device__ __nv_bfloat16 g_AreTh[NBLK*NC*NC], g_AreTl[NBLK*NC*NC];
__device__ __nv_bfloat16 g_AimTh[NBLK*NC*NC], g_AimTl[NBLK*NC*NC];
__device__ __nv_bfloat16 g_WlTh[NC*NC], g_WlTl[NC*NC];

// ---------------------------------------------------------------------------
// helpers
// ---------------------------------------------------------------------------
__device__ __forceinline__ uint32_t smem_to_u32(const void* smem_ptr) {
    uint32_t addr;
    asm("{ .reg .u64 tmp; cvta.to.shared.u64 tmp, %1; cvt.u32.u64 %0, tmp; }"
        : "=r"(addr) : "l"(smem_ptr));
    return addr;
}

#define SWZ(o) ((o) ^ (((o) >> 3) & 0x70))

__device__ __forceinline__ void ldm4(uint32_t* r, uint32_t addr) {
    asm volatile("ldmatrix.sync.aligned.m8n8.x4.shared.b16 {%0,%1,%2,%3}, [%4];"
        : "=r"(r[0]), "=r"(r[1]), "=r"(r[2]), "=r"(r[3]) : "r"(addr));
}

__device__ __forceinline__ void mma16816(float* d, const uint32_t* a, const uint32_t* b) {
    asm volatile(
        "mma.sync.aligned.m16n8k16.row.col.f32.bf16.bf16.f32 "
        "{%0,%1,%2,%3}, {%4,%5,%6,%7}, {%8,%9}, {%0,%1,%2,%3};"
        : "+f"(d[0]), "+f"(d[1]), "+f"(d[2]), "+f"(d[3])
        : "r"(a[0]), "r"(a[1]), "r"(a[2]), "r"(a[3]), "r"(b[0]), "r"(b[1]));
}

__device__ __forceinline__ unsigned short bfbits(__nv_bfloat16 h) {
    return *reinterpret_cast<unsigned short*>(&h);
}

// split 2 fp32 into packed hi / lo bf16 words
__device__ __forceinline__ void split2(float a, float b, uint32_t& hw, uint32_t& lw) {
    __nv_bfloat16 ha = __float2bfloat16(a);
    __nv_bfloat16 hb = __float2bfloat16(b);
    __nv_bfloat16 la = __float2bfloat16(a - __bfloat162float(ha));
    __nv_bfloat16 lb = __float2bfloat16(b - __bfloat162float(hb));
    hw = (uint32_t)bfbits(ha) | ((uint32_t)bfbits(hb) << 16);
    lw = (uint32_t)bfbits(la) | ((uint32_t)bfbits(lb) << 16);
}

#define CP_ASYNC(dst, src) \
    asm volatile("cp.async.cg.shared.global [%0], [%1], 16;" :: "r"(dst), "l"(src))
#define CP_COMMIT() asm volatile("cp.async.commit_group;" ::: "memory")
#define CP_WAIT0()  asm volatile("cp.async.wait_group 0;" ::: "memory")

// ---------------------------------------------------------------------------
// evecs [b][v][k] fp32 -> evT hi/lo [b][k][v] AND ev hi/lo [b][v][k]
// grid (NV/32, NK/32, NB), block (32,8)
// ---------------------------------------------------------------------------
__global__ void ev_split(const float* __restrict__ evecs,
                         __nv_bfloat16* __restrict__ eTh, __nv_bfloat16* __restrict__ eTl,
                         __nv_bfloat16* __restrict__ eh,  __nv_bfloat16* __restrict__ el)
{
    __shared__ float tile[32][33];
    const int b = blockIdx.z;
    const int v0 = blockIdx.x * 32;
    const int k0 = blockIdx.y * 32;
    const int tx = threadIdx.x, ty = threadIdx.y;
    const float* src = evecs + ((long long)b * NV + v0) * NK + k0;
#pragma unroll
    for (int j = 0; j < 32; j += 8)
        tile[ty + j][tx] = src[(long long)(ty + j) * NK + tx];
    __syncthreads();
#pragma unroll
    for (int j = 0; j < 32; j += 8) {
        // transposed
        float x = tile[tx][ty + j];
        __nv_bfloat16 h = __float2bfloat16(x);
        __nv_bfloat16 l = __float2bfloat16(x - __bfloat162float(h));
        long long o = ((long long)b * NK + k0 + ty + j) * NV + v0 + tx;
        eTh[o] = h; eTl[o] = l;
        // non-transposed
        float y = tile[ty + j][tx];
        __nv_bfloat16 h2 = __float2bfloat16(y);
        __nv_bfloat16 l2 = __float2bfloat16(y - __bfloat162float(h2));
        long long o2 = ((long long)b * NV + v0 + ty + j) * NK + k0 + tx;
        eh[o2] = h2; el[o2] = l2;
    }
}

// ---------------------------------------------------------------------------
// weight transpose+split: src [mat][Kd][128] fp32 -> dst [mat][128][Kd] bf16 h/l
// grid (Kd/32, 4, nMat), block (32,8)
// ---------------------------------------------------------------------------
__global__ void w_split(const float* __restrict__ src,
                        __nv_bfloat16* __restrict__ dh, __nv_bfloat16* __restrict__ dl,
                        int Kd)
{
    __shared__ float tile[32][33];
    const int mat = blockIdx.z;
    const int k0 = blockIdx.x * 32;
    const int n0 = blockIdx.y * 32;
    const int tx = threadIdx.x, ty = threadIdx.y;
    const float* s = src + (long long)mat * Kd * 128;
    dh += (long long)mat * 128 * Kd;
    dl += (long long)mat * 128 * Kd;
#pragma unroll
    for (int j = 0; j < 32; j += 8)
        tile[ty + j][tx] = s[(long long)(k0 + ty + j) * 128 + n0 + tx];
    __syncthreads();
#pragma unroll
    for (int j = 0; j < 32; j += 8) {
        float x = tile[tx][ty + j];   // src[k0+tx][n0+ty+j]
        __nv_bfloat16 h = __float2bfloat16(x);
        __nv_bfloat16 l = __float2bfloat16(x - __bfloat162float(h));
        long long o = (long long)(n0 + ty + j) * Kd + k0 + tx;
        dh[o] = h; dl[o] = l;
    }
}

// ---------------------------------------------------------------------------
// mm_mma: GXE/GYE = gradX/gradY @ evecs via bf16x3; outputs pre-split bf16.
// grid (NV/128, NB, 2), 256 threads, 64 KB dyn smem.
// ---------------------------------------------------------------------------
#define SM_MM_TOTAL 65536

__global__ __launch_bounds__(256) void mm_mma(
    const float* __restrict__ gradX, const float* __restrict__ gradY,
    const __nv_bfloat16* __restrict__ evTh, const __nv_bfloat16* __restrict__ evTl,
    __nv_bfloat16* __restrict__ GXEh, __nv_bfloat16* __restrict__ GXEl,
    __nv_bfloat16* __restrict__ GYEh, __nv_bfloat16* __restrict__ GYEl)
{
    extern __shared__ char smem[];
    char* sAh = smem;
    char* sAl = smem + 16384;
    const uint32_t base = smem_to_u32(smem);
    const uint32_t uAh = base, uAl = base + 16384;
    const uint32_t uBh = base + 32768, uBl = base + 49152;

    const int tid  = threadIdx.x;
    const int wid  = tid >> 5;
    const int lane = tid & 31;

    const int b    = blockIdx.y;
    const int row0 = blockIdx.x * 128;
    const int mat  = blockIdx.z;

    const float* Abase = (mat ? gradY : gradX)
                         + (long long)b * NV * NV + (long long)row0 * NV;
    const __nv_bfloat16* Bh = evTh + (long long)b * NK * NV;
    const __nv_bfloat16* Bl = evTl + (long long)b * NK * NV;
    __nv_bfloat16* Ch = (mat ? GYEh : GXEh) + (long long)b * NV * NK + (long long)row0 * NK;
    __nv_bfloat16* Cl = (mat ? GYEl : GXEl) + (long long)b * NV * NK + (long long)row0 * NK;

    const int wr  = wid & 3;
    const int wc  = wid >> 2;
    const int rw0 = wr * 32;
    const int cw0 = wc * 64;

    const int grp = lane >> 3;
    const int lr  = lane & 7;

    float acc[2][8][4];
#pragma unroll
    for (int mi = 0; mi < 2; mi++)
#pragma unroll
        for (int ni = 0; ni < 8; ni++)
#pragma unroll
            for (int q = 0; q < 4; q++) acc[mi][ni][q] = 0.f;

    for (int k0 = 0; k0 < NV; k0 += 64) {
        __syncthreads();
#pragma unroll
        for (int g = 0; g < 4; g++) {
            const int G   = tid + 256 * g;
            const int row = G >> 3;
            const int v8  = (G & 7) * 8;
            const uint32_t sw = SWZ((uint32_t)(row * 128 + v8 * 2));
            CP_ASYNC(uBh + sw, Bh + (long long)row * NV + k0 + v8);
            CP_ASYNC(uBl + sw, Bl + (long long)row * NV + k0 + v8);
        }
        CP_COMMIT();

#pragma unroll
        for (int g = 0; g < 4; g++) {
            const int G   = tid + 256 * g;
            const int row = G >> 3;
            const int v8  = (G & 7) * 8;
            const float* ap = Abase + (long long)row * NV + k0 + v8;
            float4 f0 = *reinterpret_cast<const float4*>(ap);
            float4 f1 = *reinterpret_cast<const float4*>(ap + 4);
            uint32_t hw[4], lw[4];
            split2(f0.x, f0.y, hw[0], lw[0]);
            split2(f0.z, f0.w, hw[1], lw[1]);
            split2(f1.x, f1.y, hw[2], lw[2]);
            split2(f1.z, f1.w, hw[3], lw[3]);
            const uint32_t sw = SWZ((uint32_t)(row * 128 + v8 * 2));
            *reinterpret_cast<uint4*>(sAh + sw) = make_uint4(hw[0], hw[1], hw[2], hw[3]);
            *reinterpret_cast<uint4*>(sAl + sw) = make_uint4(lw[0], lw[1], lw[2], lw[3]);
        }
        CP_WAIT0();
        __syncthreads();

#pragma unroll
        for (int ks = 0; ks < 64; ks += 16) {
            uint32_t offA[2], offB[4];
#pragma unroll
            for (int mi = 0; mi < 2; mi++) {
                const int ar = rw0 + mi * 16 + (grp & 1) * 8 + lr;
                const int ac = ks + (grp >> 1) * 8;
                offA[mi] = SWZ((uint32_t)(ar * 128 + ac * 2));
            }
#pragma unroll
            for (int nb = 0; nb < 4; nb++) {
                const int brow = cw0 + nb * 16 + (grp >> 1) * 8 + lr;
                const int bc = ks + (grp & 1) * 8;
                offB[nb] = SWZ((uint32_t)(brow * 128 + bc * 2));
            }
#pragma unroll
            for (int t = 0; t < 3; t++) {
                const uint32_t ab = (t == 2) ? uAl : uAh;
                const uint32_t bb = (t == 1) ? uBl : uBh;
                uint32_t afr[2][4], bfr[4][4];
#pragma unroll
                for (int mi = 0; mi < 2; mi++) ldm4(afr[mi], ab + offA[mi]);
#pragma unroll
                for (int nb = 0; nb < 4; nb++) ldm4(bfr[nb], bb + offB[nb]);
#pragma unroll
                for (int mi = 0; mi < 2; mi++)
#pragma unroll
                    for (int ni = 0; ni < 8; ni++)
                        mma16816(acc[mi][ni], afr[mi], &bfr[ni >> 1][(ni & 1) * 2]);
            }
        }
    }

    // epilogue: write split bf16 hi/lo
    const int orow  = lane >> 2;
    const int ocol2 = (lane & 3) * 2;
#pragma unroll
    for (int mi = 0; mi < 2; mi++)
#pragma unroll
        for (int ni = 0; ni < 8; ni++) {
            const int r = rw0 + mi * 16 + orow;
            const int c = cw0 + ni * 8 + ocol2;
            uint32_t hw, lw;
            split2(acc[mi][ni][0], acc[mi][ni][1], hw, lw);
            *reinterpret_cast<uint32_t*>(&Ch[(long long)r * NK + c]) = hw;
            *reinterpret_cast<uint32_t*>(&Cl[(long long)r * NK + c]) = lw;
            split2(acc[mi][ni][2], acc[mi][ni][3], hw, lw);
            *reinterpret_cast<uint32_t*>(&Ch[(long long)(r + 8) * NK + c]) = hw;
            *reinterpret_cast<uint32_t*>(&Cl[(long long)(r + 8) * NK + c]) = lw;
        }
}

// ---------------------------------------------------------------------------
// Generic mma GEMM: C[M,128] = act(A[M,Kd] @ B^T + bias [+C])
//   B pre-split bf16 [128][Kd] (hi/lo).  A: fp32 on-the-fly OR pre-split bf16.
//   Output: fp32 (bias/relu/beta) or split bf16 pair.
// grid (M/128, nBatch), 256 threads, 64 KB dyn smem.
// ---------------------------------------------------------------------------
__global__ __launch_bounds__(256) void gemm_mma(
    const void* __restrict__ A0, const void* __restrict__ A1, int ldA, long long sA,
    const __nv_bfloat16* __restrict__ Bh, const __nv_bfloat16* __restrict__ Bl, long long sB,
    const float* __restrict__ bias,
    void* __restrict__ C0, void* __restrict__ C1, int ldC, long long sC,
    int Kd, int flags)
{
    extern __shared__ char smem[];
    char* sAh = smem;
    char* sAl = smem + 16384;
    const uint32_t base = smem_to_u32(smem);
    const uint32_t uAh = base, uAl = base + 16384;
    const uint32_t uBh = base + 32768, uBl = base + 49152;

    const int tid  = threadIdx.x;
    const int lane = tid & 31;
    const int wid  = tid >> 5;

    const int b    = blockIdx.y;
    const int row0 = blockIdx.x * 128;

    const int aSplit = flags & F_ASPLIT;
    const float* Af = nullptr;
    const __nv_bfloat16 *Ahp = nullptr, *Alp = nullptr;
    if (aSplit) {
        Ahp = (const __nv_bfloat16*)A0 + (long long)b * sA + (long long)row0 * ldA;
        Alp = (const __nv_bfloat16*)A1 + (long long)b * sA + (long long)row0 * ldA;
    } else {
        Af  = (const float*)A0 + (long long)b * sA + (long long)row0 * ldA;
    }
    Bh += (long long)b * sB;
    Bl += (long long)b * sB;

    float* Cf = nullptr; __nv_bfloat16 *Ch = nullptr, *Cl = nullptr;
    if (flags & F_OSPLIT) {
        Ch = (__nv_bfloat16*)C0 + (long long)b * sC;
        Cl = (__nv_bfloat16*)C1 + (long long)b * sC;
    } else {
        Cf = (float*)C0 + (long long)b * sC;
    }

    const int wr  = wid & 3;
    const int wc  = wid >> 2;
    const int rw0 = wr * 32;
    const int cw0 = wc * 64;
    const int grp = lane >> 3;
    const int lr  = lane & 7;

    float acc[2][8][4];
#pragma unroll
    for (int mi = 0; mi < 2; mi++)
#pragma unroll
        for (int ni = 0; ni < 8; ni++)
#pragma unroll
            for (int q = 0; q < 4; q++) acc[mi][ni][q] = 0.f;

    for (int k0 = 0; k0 < Kd; k0 += 64) {
        __syncthreads();
#pragma unroll
        for (int g = 0; g < 4; g++) {
            const int G   = tid + 256 * g;
            const int row = G >> 3;
            const int v8  = (G & 7) * 8;
            const uint32_t sw = SWZ((uint32_t)(row * 128 + v8 * 2));
            CP_ASYNC(uBh + sw, Bh + (long long)row * Kd + k0 + v8);
            CP_ASYNC(uBl + sw, Bl + (long long)row * Kd + k0 + v8);
        }
        if (aSplit) {
#pragma unroll
            for (int g = 0; g < 4; g++) {
                const int G   = tid + 256 * g;
                const int row = G >> 3;
                const int v8  = (G & 7) * 8;
                const uint32_t sw = SWZ((uint32_t)(row * 128 + v8 * 2));
                CP_ASYNC(uAh + sw, Ahp + (long long)row * ldA + k0 + v8);
                CP_ASYNC(uAl + sw, Alp + (long long)row * ldA + k0 + v8);
            }
            CP_COMMIT();
        } else {
            CP_COMMIT();
#pragma unroll
            for (int g = 0; g < 4; g++) {
                const int G   = tid + 256 * g;
                const int row = G >> 3;
                const int v8  = (G & 7) * 8;
                const float* ap = Af + (long long)row * ldA + k0 + v8;
                float4 f0 = *reinterpret_cast<const float4*>(ap);
                float4 f1 = *reinterpret_cast<const float4*>(ap + 4);
                uint32_t hw[4], lw[4];
                split2(f0.x, f0.y, hw[0], lw[0]);
                split2(f0.z, f0.w, hw[1], lw[1]);
                split2(f1.x, f1.y, hw[2], lw[2]);
                split2(f1.z, f1.w, hw[3], lw[3]);
                const uint32_t sw = SWZ((uint32_t)(row * 128 + v8 * 2));
                *reinterpret_cast<uint4*>(sAh + sw) = make_uint4(hw[0], hw[1], hw[2], hw[3]);
                *reinterpret_cast<uint4*>(sAl + sw) = make_uint4(lw[0], lw[1], lw[2], lw[3]);
            }
        }
        CP_WAIT0();
        __syncthreads();

#pragma unroll
        for (int ks = 0; ks < 64; ks += 16) {
            uint32_t offA[2], offB[4];
#pragma unroll
            for (int mi = 0; mi < 2; mi++) {
                const int ar = rw0 + mi * 16 + (grp & 1) * 8 + lr;
                const int ac = ks + (grp >> 1) * 8;
                offA[mi] = SWZ((uint32_t)(ar * 128 + ac * 2));
            }
#pragma unroll
            for (int nb = 0; nb < 4; nb++) {
                const int brow = cw0 + nb * 16 + (grp >> 1) * 8 + lr;
                const int bc = ks + (grp & 1) * 8;
                offB[nb] = SWZ((uint32_t)(brow * 128 + bc * 2));
            }
#pragma unroll
            for (int t = 0; t < 3; t++) {
                const uint32_t ab = (t == 2) ? uAl : uAh;
                const uint32_t bb = (t == 1) ? uBl : uBh;
                uint32_t afr[2][4], bfr[4][4];
#pragma unroll
                for (int mi = 0; mi < 2; mi++) ldm4(afr[mi], ab + offA[mi]);
#pragma unroll
                for (int nb = 0; nb < 4; nb++) ldm4(bfr[nb], bb + offB[nb]);
#pragma unroll
                for (int mi = 0; mi < 2; mi++)
#pragma unroll
                    for (int ni = 0; ni < 8; ni++)
                        mma16816(acc[mi][ni], afr[mi], &bfr[ni >> 1][(ni & 1) * 2]);
            }
        }
    }

    const int orow  = lane >> 2;
    const int ocol2 = (lane & 3) * 2;
#pragma unroll
    for (int mi = 0; mi < 2; mi++)
#pragma unroll
        for (int ni = 0; ni < 8; ni++) {
            const int c = cw0 + ni * 8 + ocol2;
            float v[4] = {acc[mi][ni][0], acc[mi][ni][1], acc[mi][ni][2], acc[mi][ni][3]};
            if (bias) {
                float b0v = bias[c], b1v = bias[c + 1];
                v[0] += b0v; v[1] += b1v; v[2] += b0v; v[3] += b1v;
            }
            const long long r1 = row0 + rw0 + mi * 16 + orow;
            const long long r2 = r1 + 8;
            if (flags & F_BETA) {
                float2 p1 = *reinterpret_cast<const float2*>(&Cf[r1 * ldC + c]);
                float2 p2 = *reinterpret_cast<const float2*>(&Cf[r2 * ldC + c]);
                v[0] += p1.x; v[1] += p1.y; v[2] += p2.x; v[3] += p2.y;
            }
            if (flags & F_RELU) {
                v[0] = fmaxf(v[0], 0.f); v[1] = fmaxf(v[1], 0.f);
                v[2] = fmaxf(v[2], 0.f); v[3] = fmaxf(v[3], 0.f);
            }
            if (flags & F_OSPLIT) {
                uint32_t hw, lw;
                split2(v[0], v[1], hw, lw);
                *reinterpret_cast<uint32_t*>(&Ch[r1 * ldC + c]) = hw;
                *reinterpret_cast<uint32_t*>(&Cl[r1 * ldC + c]) = lw;
                split2(v[2], v[3], hw, lw);
                *reinterpret_cast<uint32_t*>(&Ch[r2 * ldC + c]) = hw;
                *reinterpret_cast<uint32_t*>(&Cl[r2 * ldC + c]) = lw;
            } else {
                *reinterpret_cast<float2*>(&Cf[r1 * ldC + c]) = make_float2(v[0], v[1]);
                *reinterpret_cast<float2*>(&Cf[r2 * ldC + c]) = make_float2(v[2], v[3]);
            }
        }
}

// ---------------------------------------------------------------------------
// complex_mma: br = gx@Are - gy@Aim; bi = gy@Are + gx@Aim;
//              f[:,256:384] = tanh(gx*br + gy*bi)
// A operands pre-split bf16 [b][v][128]; weights pre-split [128][128].
// grid (NV/64, NB), 256 threads, 112 KB dyn smem.
// ---------------------------------------------------------------------------
#define SM_CX (112 * 1024)

__global__ __launch_bounds__(256) void complex_mma(
    const __nv_bfloat16* __restrict__ gxh, const __nv_bfloat16* __restrict__ gxl,
    const __nv_bfloat16* __restrict__ gyh, const __nv_bfloat16* __restrict__ gyl,
    const __nv_bfloat16* __restrict__ BReh, const __nv_bfloat16* __restrict__ BRel,
    const __nv_bfloat16* __restrict__ BImh, const __nv_bfloat16* __restrict__ BIml,
    float* __restrict__ f)
{
    extern __shared__ char smem[];
    const uint32_t base = smem_to_u32(smem);
    const uint32_t aGXh = base,          aGXl = base + 8192;
    const uint32_t aGYh = base + 16384,  aGYl = base + 24576;
    const uint32_t aGNh = base + 32768,  aGNl = base + 40960;
    const uint32_t bReh = base + 49152,  bRel = base + 65536;
    const uint32_t bImh = base + 81920,  bIml = base + 98304;

    const int tid  = threadIdx.x;
    const int lane = tid & 31;
    const int wid  = tid >> 5;

    const int b    = blockIdx.y;
    const int row0 = blockIdx.x * 64;
    const long long aoff = (long long)b * NV * NC + (long long)row0 * NC;
    gxh += aoff; gxl += aoff; gyh += aoff; gyl += aoff;

    const int wr  = wid & 3;
    const int wc  = wid >> 2;
    const int rw0 = wr * 16;
    const int cw0 = wc * 64;
    const int grp = lane >> 3;
    const int lr  = lane & 7;

    float br[8][4], bi[8][4];
#pragma unroll
    for (int ni = 0; ni < 8; ni++)
#pragma unroll
        for (int q = 0; q < 4; q++) { br[ni][q] = 0.f; bi[ni][q] = 0.f; }

    for (int k0 = 0; k0 < NC; k0 += 64) {
        __syncthreads();
        // B tiles (128 rows x 64 k): 4 groups
#pragma unroll
        for (int g = 0; g < 4; g++) {
            const int G   = tid + 256 * g;
            const int row = G >> 3;
            const int v8  = (G & 7) * 8;
            const uint32_t sw = SWZ((uint32_t)(row * 128 + v8 * 2));
            CP_ASYNC(bReh + sw, BReh + (long long)row * NC + k0 + v8);
            CP_ASYNC(bRel + sw, BRel + (long long)row * NC + k0 + v8);
            CP_ASYNC(bImh + sw, BImh + (long long)row * NC + k0 + v8);
            CP_ASYNC(bIml + sw, BIml + (long long)row * NC + k0 + v8);
        }
        // gx tiles (64 rows): 2 groups
#pragma unroll
        for (int g = 0; g < 2; g++) {
            const int G   = tid + 256 * g;
            const int row = G >> 3;
            const int v8  = (G & 7) * 8;
            const uint32_t sw = SWZ((uint32_t)(row * 128 + v8 * 2));
            CP_ASYNC(aGXh + sw, gxh + (long long)row * NC + k0 + v8);
            CP_ASYNC(aGXl + sw, gxl + (long long)row * NC + k0 + v8);
        }
        CP_COMMIT();
        // gy + negated copy (manual loads)
#pragma unroll
        for (int g = 0; g < 2; g++) {
            const int G   = tid + 256 * g;
            const int row = G >> 3;
            const int v8  = (G & 7) * 8;
            const uint32_t sw = SWZ((uint32_t)(row * 128 + v8 * 2));
            uint4 th = *reinterpret_cast<const uint4*>(gyh + (long long)row * NC + k0 + v8);
            uint4 tl = *reinterpret_cast<const uint4*>(gyl + (long long)row * NC + k0 + v8);
            *reinterpret_cast<uint4*>(smem + (aGYh - base) + sw) = th;
            *reinterpret_cast<uint4*>(smem + (aGYl - base) + sw) = tl;
            th.x ^= 0x80008000u; th.y ^= 0x80008000u; th.z ^= 0x80008000u; th.w ^= 0x80008000u;
            tl.x ^= 0x80008000u; tl.y ^= 0x80008000u; tl.z ^= 0x80008000u; tl.w ^= 0x80008000u;
            *reinterpret_cast<uint4*>(smem + (aGNh - base) + sw) = th;
            *reinterpret_cast<uint4*>(smem + (aGNl - base) + sw) = tl;
        }
        CP_WAIT0();
        __syncthreads();

#pragma unroll
        for (int ks = 0; ks < 64; ks += 16) {
            const int ar = rw0 + (grp & 1) * 8 + lr;
            const int ac = ks + (grp >> 1) * 8;
            const uint32_t offA = SWZ((uint32_t)(ar * 128 + ac * 2));
            uint32_t offB[4];
#pragma unroll
            for (int nb = 0; nb < 4; nb++) {
                const int brow = cw0 + nb * 16 + (grp >> 1) * 8 + lr;
                const int bc = ks + (grp & 1) * 8;
                offB[nb] = SWZ((uint32_t)(brow * 128 + bc * 2));
            }
            uint32_t fgxh[4], fgxl[4], fgyh[4], fgyl[4], fgnh[4], fgnl[4];
            ldm4(fgxh, aGXh + offA); ldm4(fgxl, aGXl + offA);
            ldm4(fgyh, aGYh + offA); ldm4(fgyl, aGYl + offA);
            ldm4(fgnh, aGNh + offA); ldm4(fgnl, aGNl + offA);

            uint32_t bfr[4][4];
            // Are hi: br += gxh+gxl, bi += gyh+gyl
#pragma unroll
            for (int nb = 0; nb < 4; nb++) ldm4(bfr[nb], bReh + offB[nb]);
#pragma unroll
            for (int ni = 0; ni < 8; ni++) {
                const uint32_t* bb = &bfr[ni >> 1][(ni & 1) * 2];
                mma16816(br[ni], fgxh, bb); mma16816(br[ni], fgxl, bb);
                mma16816(bi[ni], fgyh, bb); mma16816(bi[ni], fgyl, bb);
            }
            // Are lo: br += gxh, bi += gyh
#pragma unroll
            for (int nb = 0; nb < 4; nb++) ldm4(bfr[nb], bRel + offB[nb]);
#pragma unroll
            for (int ni = 0; ni < 8; ni++) {
                const uint32_t* bb = &bfr[ni >> 1][(ni & 1) * 2];
                mma16816(br[ni], fgxh, bb);
                mma16816(bi[ni], fgyh, bb);
            }
            // Aim hi: br += (-gy)h + (-gy)l, bi += gxh + gxl
#pragma unroll
            for (int nb = 0; nb < 4; nb++) ldm4(bfr[nb], bImh + offB[nb]);
#pragma unroll
            for (int ni = 0; ni < 8; ni++) {
                const uint32_t* bb = &bfr[ni >> 1][(ni & 1) * 2];
                mma16816(br[ni], fgnh, bb); mma16816(br[ni], fgnl, bb);
                mma16816(bi[ni], fgxh, bb); mma16816(bi[ni], fgxl, bb);
            }
            // Aim lo: br += (-gy)h, bi += gxh
#pragma unroll
            for (int nb = 0; nb < 4; nb++) ldm4(bfr[nb], bIml + offB[nb]);
#pragma unroll
            for (int ni = 0; ni < 8; ni++) {
                const uint32_t* bb = &bfr[ni >> 1][(ni & 1) * 2];
                mma16816(br[ni], fgnh, bb);
                mma16816(bi[ni], fgxh, bb);
            }
        }
    }

    // epilogue: gfeat = tanh(gx*br + gy*bi) -> f cols [256:384]
    const int orow  = lane >> 2;
    const int ocol2 = (lane & 3) * 2;
#pragma unroll
    for (int ni = 0; ni < 8; ni++) {
        const int c = cw0 + ni * 8 + ocol2;
#pragma unroll
        for (int h = 0; h < 2; h++) {
            const int rl = rw0 + orow + h * 8;
            uint32_t xh = *reinterpret_cast<const uint32_t*>(&gxh[(long long)rl * NC + c]);
            uint32_t xl = *reinterpret_cast<const uint32_t*>(&gxl[(long long)rl * NC + c]);
            uint32_t yh = *reinterpret_cast<const uint32_t*>(&gyh[(long long)rl * NC + c]);
            uint32_t yl = *reinterpret_cast<const uint32_t*>(&gyl[(long long)rl * NC + c]);
            float gx0 = __bfloat162float(__ushort_as_bfloat16((unsigned short)(xh & 0xFFFF)))
                      + __bfloat162float(__ushort_as_bfloat16((unsigned short)(xl & 0xFFFF)));
            float gx1 = __bfloat162float(__ushort_as_bfloat16((unsigned short)(xh >> 16)))
                      + __bfloat162float(__ushort_as_bfloat16((unsigned short)(xl >> 16)));
            float gy0 = __bfloat162float(__ushort_as_bfloat16((unsigned short)(yh & 0xFFFF)))
                      + __bfloat162float(__ushort_as_bfloat16((unsigned short)(yl & 0xFFFF)));
            float gy1 = __bfloat162float(__ushort_as_bfloat16((unsigned short)(yh >> 16)))
                      + __bfloat162float(__ushort_as_bfloat16((unsigned short)(yl >> 16)));
            float o0 = tanhf(gx0 * br[ni][h * 2]     + gy0 * bi[ni][h * 2]);
            float o1 = tanhf(gx1 * br[ni][h * 2 + 1] + gy1 * bi[ni][h * 2 + 1]);
            *reinterpret_cast<float2*>(
                &f[((long long)b * NV + row0 + rl) * NMLP + 256 + c]) = make_float2(o0, o1);
        }
    }
}

// ---------------------------------------------------------------------------
// Small fp32 GEMM (only the x_in @ Wf feature GEMM, K=16)
// ---------------------------------------------------------------------------
__global__ __launch_bounds__(256) void gemm_n128(
    const float* __restrict__ A, int ldA,
    const float* __restrict__ W,
    const float* __restrict__ bias,
    float* __restrict__ C, int ldC,
    int Kd)
{
    __shared__ float As[16][68];
    __shared__ float Ws[16][128];

    const int row0 = blockIdx.x * 64;
    const int tid  = threadIdx.x;
    const int am  = tid >> 2;
    const int ak4 = (tid & 3) * 4;
    const int tx  = tid & 31;
    const int ty  = tid >> 5;
    const int c0  = tx * 4;
    const int r0  = ty * 8;

    float acc[8][4];
#pragma unroll
    for (int i = 0; i < 8; i++)
#pragma unroll
        for (int j = 0; j < 4; j++) acc[i][j] = 0.f;

    for (int k0 = 0; k0 < Kd; k0 += 16) {
        float4 av = *reinterpret_cast<const float4*>(
            &A[(long long)(row0 + am) * ldA + k0 + ak4]);
        const int i0 = tid * 2, i1 = i0 + 1;
        float4 wv0 = *reinterpret_cast<const float4*>(
            &W[(long long)(k0 + (i0 >> 5)) * 128 + (i0 & 31) * 4]);
        float4 wv1 = *reinterpret_cast<const float4*>(
            &W[(long long)(k0 + (i1 >> 5)) * 128 + (i1 & 31) * 4]);
        __syncthreads();
        As[ak4 + 0][am] = av.x; As[ak4 + 1][am] = av.y;
        As[ak4 + 2][am] = av.z; As[ak4 + 3][am] = av.w;
        *reinterpret_cast<float4*>(&Ws[i0 >> 5][(i0 & 31) * 4]) = wv0;
        *reinterpret_cast<float4*>(&Ws[i1 >> 5][(i1 & 31) * 4]) = wv1;
        __syncthreads();
#pragma unroll
        for (int kk = 0; kk < 16; kk++) {
            float4 w = *reinterpret_cast<const float4*>(&Ws[kk][c0]);
            float a[8];
#pragma unroll
            for (int i = 0; i < 8; i++) a[i] = As[kk][r0 + i];
#pragma unroll
            for (int i = 0; i < 8; i++) {
                acc[i][0] = fmaf(a[i], w.x, acc[i][0]);
                acc[i][1] = fmaf(a[i], w.y, acc[i][1]);
                acc[i][2] = fmaf(a[i], w.z, acc[i][2]);
                acc[i][3] = fmaf(a[i], w.w, acc[i][3]);
            }
        }
    }
    float4 bv = *reinterpret_cast<const float4*>(&bias[c0]);
#pragma unroll
    for (int i = 0; i < 8; i++) {
        long long off = (long long)(row0 + r0 + i) * ldC + c0;
        float4 r;
        r.x = acc[i][0] + bv.x; r.y = acc[i][1] + bv.y;
        r.z = acc[i][2] + bv.z; r.w = acc[i][3] + bv.w;
        *reinterpret_cast<float4*>(&C[off]) = r;
    }
}

// ---------------------------------------------------------------------------
// Spectral projection split-K stage 1 (NSLICE=64, 64 vertices per slice)
// ---------------------------------------------------------------------------
__global__ __launch_bounds__(256) void spec1(
    const float* __restrict__ evecs, const float* __restrict__ f,
    const float* __restrict__ mass, float* __restrict__ P)
{
    const int b  = blockIdx.y;
    const int sl = blockIdx.x;
    const int v0base = sl * (NV / NSLICE);   // 64 vertices per slice

    __shared__ float E[32][132], X[32][132];

    const float* ev = evecs + (long long)b * NV * NK;
    const float* xb = f + (long long)b * NV * NMLP;
    const float* mb = mass + b * NV;

    const int tid = threadIdx.x;
    const int vr = tid >> 3;
    const int cb = (tid & 7) * 16;
    const int r0 = (tid >> 4) * 8;
    const int c0 = (tid & 15) * 8;

    float acc[8][8];
#pragma unroll
    for (int i = 0; i < 8; i++)
#pragma unroll
        for (int j = 0; j < 8; j++) acc[i][j] = 0.f;

    for (int v0 = v0base; v0 < v0base + NV / NSLICE; v0 += 32) {
        const float* er = &ev[(long long)(v0 + vr) * NK + cb];
        const float* xr = &xb[(long long)(v0 + vr) * NMLP + cb];
        const float m = mb[v0 + vr];
        float4 e0 = *reinterpret_cast<const float4*>(er + 0);
        float4 e1 = *reinterpret_cast<const float4*>(er + 4);
        float4 e2 = *reinterpret_cast<const float4*>(er + 8);
        float4 e3 = *reinterpret_cast<const float4*>(er + 12);
        float4 x0 = *reinterpret_cast<const float4*>(xr + 0);
        float4 x1 = *reinterpret_cast<const float4*>(xr + 4);
        float4 x2 = *reinterpret_cast<const float4*>(xr + 8);
        float4 x3 = *reinterpret_cast<const float4*>(xr + 12);
        __syncthreads();
        *reinterpret_cast<float4*>(&E[vr][cb + 0])  = e0;
        *reinterpret_cast<float4*>(&E[vr][cb + 4])  = e1;
        *reinterpret_cast<float4*>(&E[vr][cb + 8])  = e2;
        *reinterpret_cast<float4*>(&E[vr][cb + 12]) = e3;
        x0.x *= m; x0.y *= m; x0.z *= m; x0.w *= m;
        x1.x *= m; x1.y *= m; x1.z *= m; x1.w *= m;
        x2.x *= m; x2.y *= m; x2.z *= m; x2.w *= m;
        x3.x *= m; x3.y *= m; x3.z *= m; x3.w *= m;
        *reinterpret_cast<float4*>(&X[vr][cb + 0])  = x0;
        *reinterpret_cast<float4*>(&X[vr][cb + 4])  = x1;
        *reinterpret_cast<float4*>(&X[vr][cb + 8])  = x2;
        *reinterpret_cast<float4*>(&X[vr][cb + 12]) = x3;
        __syncthreads();
#pragma unroll
        for (int v = 0; v < 32; v++) {
            float ka[8], xa[8];
            *reinterpret_cast<float4*>(ka)     = *reinterpret_cast<const float4*>(&E[v][r0]);
            *reinterpret_cast<float4*>(ka + 4) = *reinterpret_cast<const float4*>(&E[v][r0 + 4]);
            *reinterpret_cast<float4*>(xa)     = *reinterpret_cast<const float4*>(&X[v][c0]);
            *reinterpret_cast<float4*>(xa + 4) = *reinterpret_cast<const float4*>(&X[v][c0 + 4]);
#pragma unroll
            for (int i = 0; i < 8; i++)
#pragma unroll
                for (int j = 0; j < 8; j++)
                    acc[i][j] = fmaf(ka[i], xa[j], acc[i][j]);
        }
    }
#pragma unroll
    for (int i = 0; i < 8; i++) {
        float* pr = &P[(((long long)b * NSLICE + sl) * NK + r0 + i) * NC + c0];
        *reinterpret_cast<float4*>(pr)     = make_float4(acc[i][0], acc[i][1], acc[i][2], acc[i][3]);
        *reinterpret_cast<float4*>(pr + 4) = make_float4(acc[i][4], acc[i][5], acc[i][6], acc[i][7]);
    }
}

// ---------------------------------------------------------------------------
// Spectral stage 2 + transpose + split:
//   sT[b][c][k] (bf16 hi/lo) = exp(-evals[b,k]*max(t_i[c],1e-8)) * sum_sl P
// grid (NK/32, NC/32, NB), block (32,8)
// ---------------------------------------------------------------------------
__global__ void spec2t(const float* __restrict__ P, const float* __restrict__ evals,
                       const float* __restrict__ t_i,
                       __nv_bfloat16* __restrict__ sTh, __nv_bfloat16* __restrict__ sTl)
{
    __shared__ float tile[32][33];
    const int b  = blockIdx.z;
    const int k0 = blockIdx.x * 32;
    const int c0 = blockIdx.y * 32;
    const int tx = threadIdx.x, ty = threadIdx.y;
#pragma unroll
    for (int j = 0; j < 32; j += 8) {
        const int k = k0 + ty + j;
        float acc = 0.f;
        for (int sl = 0; sl < NSLICE; sl++)
            acc += P[(((long long)b * NSLICE + sl) * NK + k) * NC + c0 + tx];
        const float ti = fmaxf(t_i[c0 + tx], 1e-8f);
        tile[ty + j][tx] = expf(-evals[b * NK + k] * ti) * acc;
    }
    __syncthreads();
#pragma unroll
    for (int j = 0; j < 32; j += 8) {
        float x = tile[tx][ty + j];     // (k = k0+tx, c = c0+ty+j)
        __nv_bfloat16 h = __float2bfloat16(x);
        __nv_bfloat16 l = __float2bfloat16(x - __bfloat162float(h));
        long long o = ((long long)b * NC + c0 + ty + j) * NK + k0 + tx;
        sTh[o] = h; sTl[o] = l;
    }
}

// ---------------------------------------------------------------------------
extern "C" void kernel_launch(void* const* d_in, const int* in_sizes, int n_in,
                              void* d_out, int out_size)
{
    const float* x_in  = (const float*)d_in[0];
    const float* mass  = (const float*)d_in[1];
    const float* evals = (const float*)d_in[2];
    const float* evecs = (const float*)d_in[3];
    const float* gradX = (const float*)d_in[4];
    const float* gradY = (const float*)d_in[5];
    const float* Wf    = (const float*)d_in[6];
    const float* bf    = (const float*)d_in[7];
    const float* Wl    = (const float*)d_in[8];
    const float* bl    = (const float*)d_in[9];
    const float* t     = (const float*)d_in[10];
    const float* Are   = (const float*)d_in[11];
    const float* Aim   = (const float*)d_in[12];
    const float* W0    = (const float*)d_in[13];
    const float* b0    = (const float*)d_in[14];
    const float* W1    = (const float*)d_in[15];
    const float* b1    = (const float*)d_in[16];
    const float* W2    = (const float*)d_in[17];
    const float* b2    = (const float*)d_in[18];
    float* out = (float*)d_out;

    float *f, *P;
    __nv_bfloat16 *evTh, *evTl, *evh, *evl, *GXEh, *GXEl, *GYEh, *GYEl;
    __nv_bfloat16 *sTh, *sTl, *gxh, *gxl, *gyh, *gyl, *h0h, *h0l, *h1h, *h1l;
    __nv_bfloat16 *W0Th, *W0Tl, *W1Th, *W1Tl, *W2Th, *W2Tl;
    __nv_bfloat16 *AreTh, *AreTl, *AimTh, *AimTl, *WlTh, *WlTl;
    cudaGetSymbolAddress((void**)&f,     g_f);
    cudaGetSymbolAddress((void**)&P,     g_P);
    cudaGetSymbolAddress((void**)&evTh,  g_evTh);
    cudaGetSymbolAddress((void**)&evTl,  g_evTl);
    cudaGetSymbolAddress((void**)&evh,   g_evh);
    cudaGetSymbolAddress((void**)&evl,   g_evl);
    cudaGetSymbolAddress((void**)&GXEh,  g_GXEh);
    cudaGetSymbolAddress((void**)&GXEl,  g_GXEl);
    cudaGetSymbolAddress((void**)&GYEh,  g_GYEh);
    cudaGetSymbolAddress((void**)&GYEl,  g_GYEl);
    cudaGetSymbolAddress((void**)&sTh,   g_sTh);
    cudaGetSymbolAddress((void**)&sTl,   g_sTl);
    cudaGetSymbolAddress((void**)&gxh,   g_gxh);
    cudaGetSymbolAddress((void**)&gxl,   g_gxl);
    cudaGetSymbolAddress((void**)&gyh,   g_gyh);
    cudaGetSymbolAddress((void**)&gyl,   g_gyl);
    cudaGetSymbolAddress((void**)&h0h,   g_h0h);
    cudaGetSymbolAddress((void**)&h0l,   g_h0l);
    cudaGetSymbolAddress((void**)&h1h,   g_h1h);
    cudaGetSymbolAddress((void**)&h1l,   g_h1l);
    cudaGetSymbolAddress((void**)&W0Th,  g_W0Th);
    cudaGetSymbolAddress((void**)&W0Tl,  g_W0Tl);
    cudaGetSymbolAddress((void**)&W1Th,  g_W1Th);
    cudaGetSymbolAddress((void**)&W1Tl,  g_W1Tl);
    cudaGetSymbolAddress((void**)&W2Th,  g_W2Th);
    cudaGetSymbolAddress((void**)&W2Tl,  g_W2Tl);
    cudaGetSymbolAddress((void**)&AreTh, g_AreTh);
    cudaGetSymbolAddress((void**)&AreTl, g_AreTl);
    cudaGetSymbolAddress((void**)&AimTh, g_AimTh);
    cudaGetSymbolAddress((void**)&AimTl, g_AimTl);
    cudaGetSymbolAddress((void**)&WlTh,  g_WlTh);
    cudaGetSymbolAddress((void**)&WlTl,  g_WlTl);

    cudaFuncSetAttribute(mm_mma, cudaFuncAttributeMaxDynamicSharedMemorySize, SM_MM_TOTAL);
    cudaFuncSetAttribute(gemm_mma, cudaFuncAttributeMaxDynamicSharedMemorySize, SM_MM_TOTAL);
    cudaFuncSetAttribute(complex_mma, cudaFuncAttributeMaxDynamicSharedMemorySize, SM_CX);

    const long long sVK = (long long)NV * NK;
    const long long sVC = (long long)NV * NC;
    const long long sVM = (long long)NV * NMLP;
    const long long sCK = (long long)NC * NK;

    // x = x_in @ Wf + bf  -> f[:, 0:128]
    gemm_n128<<<dim3(NB * NV / 64), 256>>>(x_in, NCIN, Wf, bf, f, NMLP, NCIN);

    // one-time splits
    ev_split<<<dim3(NV / 32, NK / 32, NB), dim3(32, 8)>>>(evecs, evTh, evTl, evh, evl);
    w_split<<<dim3(NMLP / 32, 4, NBLK), dim3(32, 8)>>>(W0, W0Th, W0Tl, NMLP);
    w_split<<<dim3(NC / 32, 4, NBLK), dim3(32, 8)>>>(W1, W1Th, W1Tl, NC);
    w_split<<<dim3(NC / 32, 4, NBLK), dim3(32, 8)>>>(W2, W2Th, W2Tl, NC);
    w_split<<<dim3(NC / 32, 4, NBLK), dim3(32, 8)>>>(Are, AreTh, AreTl, NC);
    w_split<<<dim3(NC / 32, 4, NBLK), dim3(32, 8)>>>(Aim, AimTh, AimTl, NC);
    w_split<<<dim3(NC / 32, 4, 1), dim3(32, 8)>>>(Wl, WlTh, WlTl, NC);

    // GXE/GYE = gradX/gradY @ evecs (tensor cores, pre-split output)
    mm_mma<<<dim3(NV / 128, NB, 2), 256, SM_MM_TOTAL>>>(
        gradX, gradY, evTh, evTl, GXEh, GXEl, GYEh, GYEl);

    for (int i = 0; i < NBLK; i++) {
        const long long wo1 = (long long)i * NC * NC;
        const long long wo0 = (long long)i * NC * NMLP;
        // s^T = exp(-evals*t_i) * (evecs^T @ (x*mass)), split-K
        spec1<<<dim3(NSLICE, NB), 256>>>(evecs, f, mass, P);
        spec2t<<<dim3(NK / 32, NC / 32, NB), dim3(32, 8)>>>(P, evals, t + i * NC, sTh, sTl);
        // x_diff = evecs @ s -> f[:, 128:256] (fp32)
        gemm_mma<<<dim3(NV / 128, NB), 256, SM_MM_TOTAL>>>(
            evh, evl, NK, sVK, sTh, sTl, sCK, nullptr,
            f + NC, nullptr, NMLP, sVM, NK, F_ASPLIT);
        // gx = GXE @ s (split out), gy = GYE @ s (split out)
        gemm_mma<<<dim3(NV / 128, NB), 256, SM_MM_TOTAL>>>(
            GXEh, GXEl, NK, sVK, sTh, sTl, sCK, nullptr,
            gxh, gxl, NC, sVC, NK, F_ASPLIT | F_OSPLIT);
        gemm_mma<<<dim3(NV / 128, NB), 256, SM_MM_TOTAL>>>(
            GYEh, GYEl, NK, sVK, sTh, sTl, sCK, nullptr,
            gyh, gyl, NC, sVC, NK, F_ASPLIT | F_OSPLIT);
        // gfeat -> f[:, 256:384]
        complex_mma<<<dim3(NV / 64, NB), 256, SM_CX>>>(
            gxh, gxl, gyh, gyl,
            AreTh + wo1, AreTl + wo1, AimTh + wo1, AimTl + wo1, f);
        // MLP
        gemm_mma<<<dim3(NB * NV / 128, 1), 256, SM_MM_TOTAL>>>(
            f, nullptr, NMLP, 0, W0Th + wo0, W0Tl + wo0, 0, b0 + i * NC,
            h0h, h0l, NC, 0, NMLP, F_RELU | F_OSPLIT);
        gemm_mma<<<dim3(NB * NV / 128, 1), 256, SM_MM_TOTAL>>>(
            h0h, h0l, NC, 0, W1Th + wo1, W1Tl + wo1, 0, b1 + i * NC,
            h1h, h1l, NC, 0, NC, F_ASPLIT | F_RELU | F_OSPLIT);
        // x += h1 @ W2 + b2 (beta into f[:, 0:128])
        gemm_mma<<<dim3(NB * NV / 128, 1), 256, SM_MM_TOTAL>>>(
            h1h, h1l, NC, 0, W2Th + wo1, W2Tl + wo1, 0, b2 + i * NC,
            f, nullptr, NMLP, 0, NC, F_ASPLIT | F_BETA);
    }

    // out = x @ Wl + bl
    gemm_mma<<<dim3(NB * NV / 128, 1), 256, SM_MM_TOTAL>>>(
        f, nullptr, NMLP, 0, WlTh, WlTl, 0, bl,
        out, nullptr, NC, 0, NC, 0);
}

// round 6
// speedup vs baseline: 2.0917x; 1.0009x over previous
#include <cuda_runtime.h>
#include <cuda_bf16.h>
#include <math.h>
#include <cstdint>

#define NB   4      // batch
#define NV   4096   // vertices
#define NK   128    // eigenbasis
#define NCIN 16
#define NC   128    // width
#define NMLP 384    // 3*NC
#define NBLK 4
#define NSLICE 64   // split-K slices for spectral projection

// flags for gemm_mma
#define F_RELU   1
#define F_BETA   2
#define F_ASPLIT 4
#define F_OSPLIT 8

// ---------------------------------------------------------------------------
// Scratch (device globals; no allocation anywhere)
// ---------------------------------------------------------------------------
__device__ float g_f[NB*NV*NMLP];                 // packed [x | x_diff | gfeat]
__device__ float g_P[NB*NSLICE*NK*NC];            // spec split-K partials
__device__ __nv_bfloat16 g_evTh[NB*NK*NV];        // evecs^T hi (K-major, for mm_mma B)
__device__ __nv_bfloat16 g_evTl[NB*NK*NV];
__device__ __nv_bfloat16 g_evh [NB*NV*NK];        // evecs hi (row-major, A operand)
__device__ __nv_bfloat16 g_evl [NB*NV*NK];
__device__ __nv_bfloat16 g_GXEh[NB*NV*NK], g_GXEl[NB*NV*NK];
__device__ __nv_bfloat16 g_GYEh[NB*NV*NK], g_GYEl[NB*NV*NK];
__device__ __nv_bfloat16 g_sTh[NB*NC*NK], g_sTl[NB*NC*NK];   // s^T [c][k]
__device__ __nv_bfloat16 g_gxh[NB*NV*NC], g_gxl[NB*NV*NC];
__device__ __nv_bfloat16 g_gyh[NB*NV*NC], g_gyl[NB*NV*NC];
__device__ __nv_bfloat16 g_h0h[NB*NV*NC], g_h0l[NB*NV*NC];
__device__ __nv_bfloat16 g_h1h[NB*NV*NC], g_h1l[NB*NV*NC];
__device__ __nv_bfloat16 g_W0Th[NBLK*NC*NMLP], g_W0Tl[NBLK*NC*NMLP];
__device__ __nv_bfloat16 g_W1Th[NBLK*NC*NC],  g_W1Tl[NBLK*NC*NC];
__device__ __nv_bfloat16 g_W2Th[NBLK*NC*NC],  g_W2Tl[NBLK*NC*NC];
__device__ __nv_bfloat16 g_AreTh[NBLK*NC*NC], g_AreTl[NBLK*NC*NC];
__device__ __nv_bfloat16 g_AimTh[NBLK*NC*NC], g_AimTl[NBLK*NC*NC];
__device__ __nv_bfloat16 g_WlTh[NC*NC], g_WlTl[NC*NC];

// ---------------------------------------------------------------------------
// helpers
// ---------------------------------------------------------------------------
__device__ __forceinline__ uint32_t smem_to_u32(const void* smem_ptr) {
    uint32_t addr;
    asm("{ .reg .u64 tmp; cvta.to.shared.u64 tmp, %1; cvt.u32.u64 %0, tmp; }"
        : "=r"(addr) : "l"(smem_ptr));
    return addr;
}

#define SWZ(o) ((o) ^ (((o) >> 3) & 0x70))

__device__ __forceinline__ void ldm4(uint32_t* r, uint32_t addr) {
    asm volatile("ldmatrix.sync.aligned.m8n8.x4.shared.b16 {%0,%1,%2,%3}, [%4];"
        : "=r"(r[0]), "=r"(r[1]), "=r"(r[2]), "=r"(r[3]) : "r"(addr));
}

__device__ __forceinline__ void mma16816(float* d, const uint32_t* a, const uint32_t* b) {
    asm volatile(
        "mma.sync.aligned.m16n8k16.row.col.f32.bf16.bf16.f32 "
        "{%0,%1,%2,%3}, {%4,%5,%6,%7}, {%8,%9}, {%0,%1,%2,%3};"
        : "+f"(d[0]), "+f"(d[1]), "+f"(d[2]), "+f"(d[3])
        : "r"(a[0]), "r"(a[1]), "r"(a[2]), "r"(a[3]), "r"(b[0]), "r"(b[1]));
}

__device__ __forceinline__ unsigned short bfbits(__nv_bfloat16 h) {
    return *reinterpret_cast<unsigned short*>(&h);
}

// split 2 fp32 into packed hi / lo bf16 words
__device__ __forceinline__ void split2(float a, float b, uint32_t& hw, uint32_t& lw) {
    __nv_bfloat16 ha = __float2bfloat16(a);
    __nv_bfloat16 hb = __float2bfloat16(b);
    __nv_bfloat16 la = __float2bfloat16(a - __bfloat162float(ha));
    __nv_bfloat16 lb = __float2bfloat16(b - __bfloat162float(hb));
    hw = (uint32_t)bfbits(ha) | ((uint32_t)bfbits(hb) << 16);
    lw = (uint32_t)bfbits(la) | ((uint32_t)bfbits(lb) << 16);
}

#define CP_ASYNC(dst, src) \
    asm volatile("cp.async.cg.shared.global [%0], [%1], 16;" :: "r"(dst), "l"(src))
#define CP_COMMIT() asm volatile("cp.async.commit_group;" ::: "memory")
#define CP_WAIT0()  asm volatile("cp.async.wait_group 0;" ::: "memory")

// ---------------------------------------------------------------------------
// evecs [b][v][k] fp32 -> evT hi/lo [b][k][v] AND ev hi/lo [b][v][k]
// grid (NV/32, NK/32, NB), block (32,8)
// ---------------------------------------------------------------------------
__global__ void ev_split(const float* __restrict__ evecs,
                         __nv_bfloat16* __restrict__ eTh, __nv_bfloat16* __restrict__ eTl,
                         __nv_bfloat16* __restrict__ eh,  __nv_bfloat16* __restrict__ el)
{
    __shared__ float tile[32][33];
    const int b = blockIdx.z;
    const int v0 = blockIdx.x * 32;
    const int k0 = blockIdx.y * 32;
    const int tx = threadIdx.x, ty = threadIdx.y;
    const float* src = evecs + ((long long)b * NV + v0) * NK + k0;
#pragma unroll
    for (int j = 0; j < 32; j += 8)
        tile[ty + j][tx] = src[(long long)(ty + j) * NK + tx];
    __syncthreads();
#pragma unroll
    for (int j = 0; j < 32; j += 8) {
        // transposed
        float x = tile[tx][ty + j];
        __nv_bfloat16 h = __float2bfloat16(x);
        __nv_bfloat16 l = __float2bfloat16(x - __bfloat162float(h));
        long long o = ((long long)b * NK + k0 + ty + j) * NV + v0 + tx;
        eTh[o] = h; eTl[o] = l;
        // non-transposed
        float y = tile[ty + j][tx];
        __nv_bfloat16 h2 = __float2bfloat16(y);
        __nv_bfloat16 l2 = __float2bfloat16(y - __bfloat162float(h2));
        long long o2 = ((long long)b * NV + v0 + ty + j) * NK + k0 + tx;
        eh[o2] = h2; el[o2] = l2;
    }
}

// ---------------------------------------------------------------------------
// weight transpose+split: src [mat][Kd][128] fp32 -> dst [mat][128][Kd] bf16 h/l
// grid (Kd/32, 4, nMat), block (32,8)
// ---------------------------------------------------------------------------
__global__ void w_split(const float* __restrict__ src,
                        __nv_bfloat16* __restrict__ dh, __nv_bfloat16* __restrict__ dl,
                        int Kd)
{
    __shared__ float tile[32][33];
    const int mat = blockIdx.z;
    const int k0 = blockIdx.x * 32;
    const int n0 = blockIdx.y * 32;
    const int tx = threadIdx.x, ty = threadIdx.y;
    const float* s = src + (long long)mat * Kd * 128;
    dh += (long long)mat * 128 * Kd;
    dl += (long long)mat * 128 * Kd;
#pragma unroll
    for (int j = 0; j < 32; j += 8)
        tile[ty + j][tx] = s[(long long)(k0 + ty + j) * 128 + n0 + tx];
    __syncthreads();
#pragma unroll
    for (int j = 0; j < 32; j += 8) {
        float x = tile[tx][ty + j];   // src[k0+tx][n0+ty+j]
        __nv_bfloat16 h = __float2bfloat16(x);
        __nv_bfloat16 l = __float2bfloat16(x - __bfloat162float(h));
        long long o = (long long)(n0 + ty + j) * Kd + k0 + tx;
        dh[o] = h; dl[o] = l;
    }
}

// ---------------------------------------------------------------------------
// mm_mma: GXE/GYE = gradX/gradY @ evecs via bf16x3; outputs pre-split bf16.
// grid (NV/128, NB, 2), 256 threads, 64 KB dyn smem.
// ---------------------------------------------------------------------------
#define SM_MM_TOTAL 65536

__global__ __launch_bounds__(256) void mm_mma(
    const float* __restrict__ gradX, const float* __restrict__ gradY,
    const __nv_bfloat16* __restrict__ evTh, const __nv_bfloat16* __restrict__ evTl,
    __nv_bfloat16* __restrict__ GXEh, __nv_bfloat16* __restrict__ GXEl,
    __nv_bfloat16* __restrict__ GYEh, __nv_bfloat16* __restrict__ GYEl)
{
    extern __shared__ char smem[];
    char* sAh = smem;
    char* sAl = smem + 16384;
    const uint32_t base = smem_to_u32(smem);
    const uint32_t uAh = base, uAl = base + 16384;
    const uint32_t uBh = base + 32768, uBl = base + 49152;

    const int tid  = threadIdx.x;
    const int wid  = tid >> 5;
    const int lane = tid & 31;

    const int b    = blockIdx.y;
    const int row0 = blockIdx.x * 128;
    const int mat  = blockIdx.z;

    const float* Abase = (mat ? gradY : gradX)
                         + (long long)b * NV * NV + (long long)row0 * NV;
    const __nv_bfloat16* Bh = evTh + (long long)b * NK * NV;
    const __nv_bfloat16* Bl = evTl + (long long)b * NK * NV;
    __nv_bfloat16* Ch = (mat ? GYEh : GXEh) + (long long)b * NV * NK + (long long)row0 * NK;
    __nv_bfloat16* Cl = (mat ? GYEl : GXEl) + (long long)b * NV * NK + (long long)row0 * NK;

    const int wr  = wid & 3;
    const int wc  = wid >> 2;
    const int rw0 = wr * 32;
    const int cw0 = wc * 64;

    const int grp = lane >> 3;
    const int lr  = lane & 7;

    float acc[2][8][4];
#pragma unroll
    for (int mi = 0; mi < 2; mi++)
#pragma unroll
        for (int ni = 0; ni < 8; ni++)
#pragma unroll
            for (int q = 0; q < 4; q++) acc[mi][ni][q] = 0.f;

    for (int k0 = 0; k0 < NV; k0 += 64) {
        __syncthreads();
#pragma unroll
        for (int g = 0; g < 4; g++) {
            const int G   = tid + 256 * g;
            const int row = G >> 3;
            const int v8  = (G & 7) * 8;
            const uint32_t sw = SWZ((uint32_t)(row * 128 + v8 * 2));
            CP_ASYNC(uBh + sw, Bh + (long long)row * NV + k0 + v8);
            CP_ASYNC(uBl + sw, Bl + (long long)row * NV + k0 + v8);
        }
        CP_COMMIT();

#pragma unroll
        for (int g = 0; g < 4; g++) {
            const int G   = tid + 256 * g;
            const int row = G >> 3;
            const int v8  = (G & 7) * 8;
            const float* ap = Abase + (long long)row * NV + k0 + v8;
            float4 f0 = *reinterpret_cast<const float4*>(ap);
            float4 f1 = *reinterpret_cast<const float4*>(ap + 4);
            uint32_t hw[4], lw[4];
            split2(f0.x, f0.y, hw[0], lw[0]);
            split2(f0.z, f0.w, hw[1], lw[1]);
            split2(f1.x, f1.y, hw[2], lw[2]);
            split2(f1.z, f1.w, hw[3], lw[3]);
            const uint32_t sw = SWZ((uint32_t)(row * 128 + v8 * 2));
            *reinterpret_cast<uint4*>(sAh + sw) = make_uint4(hw[0], hw[1], hw[2], hw[3]);
            *reinterpret_cast<uint4*>(sAl + sw) = make_uint4(lw[0], lw[1], lw[2], lw[3]);
        }
        CP_WAIT0();
        __syncthreads();

#pragma unroll
        for (int ks = 0; ks < 64; ks += 16) {
            uint32_t offA[2], offB[4];
#pragma unroll
            for (int mi = 0; mi < 2; mi++) {
                const int ar = rw0 + mi * 16 + (grp & 1) * 8 + lr;
                const int ac = ks + (grp >> 1) * 8;
                offA[mi] = SWZ((uint32_t)(ar * 128 + ac * 2));
            }
#pragma unroll
            for (int nb = 0; nb < 4; nb++) {
                const int brow = cw0 + nb * 16 + (grp >> 1) * 8 + lr;
                const int bc = ks + (grp & 1) * 8;
                offB[nb] = SWZ((uint32_t)(brow * 128 + bc * 2));
            }
#pragma unroll
            for (int t = 0; t < 3; t++) {
                const uint32_t ab = (t == 2) ? uAl : uAh;
                const uint32_t bb = (t == 1) ? uBl : uBh;
                uint32_t afr[2][4], bfr[4][4];
#pragma unroll
                for (int mi = 0; mi < 2; mi++) ldm4(afr[mi], ab + offA[mi]);
#pragma unroll
                for (int nb = 0; nb < 4; nb++) ldm4(bfr[nb], bb + offB[nb]);
#pragma unroll
                for (int mi = 0; mi < 2; mi++)
#pragma unroll
                    for (int ni = 0; ni < 8; ni++)
                        mma16816(acc[mi][ni], afr[mi], &bfr[ni >> 1][(ni & 1) * 2]);
            }
        }
    }

    // epilogue: write split bf16 hi/lo
    const int orow  = lane >> 2;
    const int ocol2 = (lane & 3) * 2;
#pragma unroll
    for (int mi = 0; mi < 2; mi++)
#pragma unroll
        for (int ni = 0; ni < 8; ni++) {
            const int r = rw0 + mi * 16 + orow;
            const int c = cw0 + ni * 8 + ocol2;
            uint32_t hw, lw;
            split2(acc[mi][ni][0], acc[mi][ni][1], hw, lw);
            *reinterpret_cast<uint32_t*>(&Ch[(long long)r * NK + c]) = hw;
            *reinterpret_cast<uint32_t*>(&Cl[(long long)r * NK + c]) = lw;
            split2(acc[mi][ni][2], acc[mi][ni][3], hw, lw);
            *reinterpret_cast<uint32_t*>(&Ch[(long long)(r + 8) * NK + c]) = hw;
            *reinterpret_cast<uint32_t*>(&Cl[(long long)(r + 8) * NK + c]) = lw;
        }
}

// ---------------------------------------------------------------------------
// Generic mma GEMM: C[M,128] = act(A[M,Kd] @ B^T + bias [+C])
//   B pre-split bf16 [128][Kd] (hi/lo).  A: fp32 on-the-fly OR pre-split bf16.
//   Output: fp32 (bias/relu/beta) or split bf16 pair.
// grid (M/128, nBatch), 256 threads, 64 KB dyn smem.
// ---------------------------------------------------------------------------
__global__ __launch_bounds__(256) void gemm_mma(
    const void* __restrict__ A0, const void* __restrict__ A1, int ldA, long long sA,
    const __nv_bfloat16* __restrict__ Bh, const __nv_bfloat16* __restrict__ Bl, long long sB,
    const float* __restrict__ bias,
    void* __restrict__ C0, void* __restrict__ C1, int ldC, long long sC,
    int Kd, int flags)
{
    extern __shared__ char smem[];
    char* sAh = smem;
    char* sAl = smem + 16384;
    const uint32_t base = smem_to_u32(smem);
    const uint32_t uAh = base, uAl = base + 16384;
    const uint32_t uBh = base + 32768, uBl = base + 49152;

    const int tid  = threadIdx.x;
    const int lane = tid & 31;
    const int wid  = tid >> 5;

    const int b    = blockIdx.y;
    const int row0 = blockIdx.x * 128;

    const int aSplit = flags & F_ASPLIT;
    const float* Af = nullptr;
    const __nv_bfloat16 *Ahp = nullptr, *Alp = nullptr;
    if (aSplit) {
        Ahp = (const __nv_bfloat16*)A0 + (long long)b * sA + (long long)row0 * ldA;
        Alp = (const __nv_bfloat16*)A1 + (long long)b * sA + (long long)row0 * ldA;
    } else {
        Af  = (const float*)A0 + (long long)b * sA + (long long)row0 * ldA;
    }
    Bh += (long long)b * sB;
    Bl += (long long)b * sB;

    float* Cf = nullptr; __nv_bfloat16 *Ch = nullptr, *Cl = nullptr;
    if (flags & F_OSPLIT) {
        Ch = (__nv_bfloat16*)C0 + (long long)b * sC;
        Cl = (__nv_bfloat16*)C1 + (long long)b * sC;
    } else {
        Cf = (float*)C0 + (long long)b * sC;
    }

    const int wr  = wid & 3;
    const int wc  = wid >> 2;
    const int rw0 = wr * 32;
    const int cw0 = wc * 64;
    const int grp = lane >> 3;
    const int lr  = lane & 7;

    float acc[2][8][4];
#pragma unroll
    for (int mi = 0; mi < 2; mi++)
#pragma unroll
        for (int ni = 0; ni < 8; ni++)
#pragma unroll
            for (int q = 0; q < 4; q++) acc[mi][ni][q] = 0.f;

    for (int k0 = 0; k0 < Kd; k0 += 64) {
        __syncthreads();
#pragma unroll
        for (int g = 0; g < 4; g++) {
            const int G   = tid + 256 * g;
            const int row = G >> 3;
            const int v8  = (G & 7) * 8;
            const uint32_t sw = SWZ((uint32_t)(row * 128 + v8 * 2));
            CP_ASYNC(uBh + sw, Bh + (long long)row * Kd + k0 + v8);
            CP_ASYNC(uBl + sw, Bl + (long long)row * Kd + k0 + v8);
        }
        if (aSplit) {
#pragma unroll
            for (int g = 0; g < 4; g++) {
                const int G   = tid + 256 * g;
                const int row = G >> 3;
                const int v8  = (G & 7) * 8;
                const uint32_t sw = SWZ((uint32_t)(row * 128 + v8 * 2));
                CP_ASYNC(uAh + sw, Ahp + (long long)row * ldA + k0 + v8);
                CP_ASYNC(uAl + sw, Alp + (long long)row * ldA + k0 + v8);
            }
            CP_COMMIT();
        } else {
            CP_COMMIT();
#pragma unroll
            for (int g = 0; g < 4; g++) {
                const int G   = tid + 256 * g;
                const int row = G >> 3;
                const int v8  = (G & 7) * 8;
                const float* ap = Af + (long long)row * ldA + k0 + v8;
                float4 f0 = *reinterpret_cast<const float4*>(ap);
                float4 f1 = *reinterpret_cast<const float4*>(ap + 4);
                uint32_t hw[4], lw[4];
                split2(f0.x, f0.y, hw[0], lw[0]);
                split2(f0.z, f0.w, hw[1], lw[1]);
                split2(f1.x, f1.y, hw[2], lw[2]);
                split2(f1.z, f1.w, hw[3], lw[3]);
                const uint32_t sw = SWZ((uint32_t)(row * 128 + v8 * 2));
                *reinterpret_cast<uint4*>(sAh + sw) = make_uint4(hw[0], hw[1], hw[2], hw[3]);
                *reinterpret_cast<uint4*>(sAl + sw) = make_uint4(lw[0], lw[1], lw[2], lw[3]);
            }
        }
        CP_WAIT0();
        __syncthreads();

#pragma unroll
        for (int ks = 0; ks < 64; ks += 16) {
            uint32_t offA[2], offB[4];
#pragma unroll
            for (int mi = 0; mi < 2; mi++) {
                const int ar = rw0 + mi * 16 + (grp & 1) * 8 + lr;
                const int ac = ks + (grp >> 1) * 8;
                offA[mi] = SWZ((uint32_t)(ar * 128 + ac * 2));
            }
#pragma unroll
            for (int nb = 0; nb < 4; nb++) {
                const int brow = cw0 + nb * 16 + (grp >> 1) * 8 + lr;
                const int bc = ks + (grp & 1) * 8;
                offB[nb] = SWZ((uint32_t)(brow * 128 + bc * 2));
            }
#pragma unroll
            for (int t = 0; t < 3; t++) {
                const uint32_t ab = (t == 2) ? uAl : uAh;
                const uint32_t bb = (t == 1) ? uBl : uBh;
                uint32_t afr[2][4], bfr[4][4];
#pragma unroll
                for (int mi = 0; mi < 2; mi++) ldm4(afr[mi], ab + offA[mi]);
#pragma unroll
                for (int nb = 0; nb < 4; nb++) ldm4(bfr[nb], bb + offB[nb]);
#pragma unroll
                for (int mi = 0; mi < 2; mi++)
#pragma unroll
                    for (int ni = 0; ni < 8; ni++)
                        mma16816(acc[mi][ni], afr[mi], &bfr[ni >> 1][(ni & 1) * 2]);
            }
        }
    }

    const int orow  = lane >> 2;
    const int ocol2 = (lane & 3) * 2;
#pragma unroll
    for (int mi = 0; mi < 2; mi++)
#pragma unroll
        for (int ni = 0; ni < 8; ni++) {
            const int c = cw0 + ni * 8 + ocol2;
            float v[4] = {acc[mi][ni][0], acc[mi][ni][1], acc[mi][ni][2], acc[mi][ni][3]};
            if (bias) {
                float b0v = bias[c], b1v = bias[c + 1];
                v[0] += b0v; v[1] += b1v; v[2] += b0v; v[3] += b1v;
            }
            const long long r1 = row0 + rw0 + mi * 16 + orow;
            const long long r2 = r1 + 8;
            if (flags & F_BETA) {
                float2 p1 = *reinterpret_cast<const float2*>(&Cf[r1 * ldC + c]);
                float2 p2 = *reinterpret_cast<const float2*>(&Cf[r2 * ldC + c]);
                v[0] += p1.x; v[1] += p1.y; v[2] += p2.x; v[3] += p2.y;
            }
            if (flags & F_RELU) {
                v[0] = fmaxf(v[0], 0.f); v[1] = fmaxf(v[1], 0.f);
                v[2] = fmaxf(v[2], 0.f); v[3] = fmaxf(v[3], 0.f);
            }
            if (flags & F_OSPLIT) {
                uint32_t hw, lw;
                split2(v[0], v[1], hw, lw);
                *reinterpret_cast<uint32_t*>(&Ch[r1 * ldC + c]) = hw;
                *reinterpret_cast<uint32_t*>(&Cl[r1 * ldC + c]) = lw;
                split2(v[2], v[3], hw, lw);
                *reinterpret_cast<uint32_t*>(&Ch[r2 * ldC + c]) = hw;
                *reinterpret_cast<uint32_t*>(&Cl[r2 * ldC + c]) = lw;
            } else {
                *reinterpret_cast<float2*>(&Cf[r1 * ldC + c]) = make_float2(v[0], v[1]);
                *reinterpret_cast<float2*>(&Cf[r2 * ldC + c]) = make_float2(v[2], v[3]);
            }
        }
}

// ---------------------------------------------------------------------------
// complex_mma: br = gx@Are - gy@Aim; bi = gy@Are + gx@Aim;
//              f[:,256:384] = tanh(gx*br + gy*bi)
// A operands pre-split bf16 [b][v][128]; weights pre-split [128][128].
// grid (NV/64, NB), 256 threads, 112 KB dyn smem.
// ---------------------------------------------------------------------------
#define SM_CX (112 * 1024)

__global__ __launch_bounds__(256) void complex_mma(
    const __nv_bfloat16* __restrict__ gxh, const __nv_bfloat16* __restrict__ gxl,
    const __nv_bfloat16* __restrict__ gyh, const __nv_bfloat16* __restrict__ gyl,
    const __nv_bfloat16* __restrict__ BReh, const __nv_bfloat16* __restrict__ BRel,
    const __nv_bfloat16* __restrict__ BImh, const __nv_bfloat16* __restrict__ BIml,
    float* __restrict__ f)
{
    extern __shared__ char smem[];
    const uint32_t base = smem_to_u32(smem);
    const uint32_t aGXh = base,          aGXl = base + 8192;
    const uint32_t aGYh = base + 16384,  aGYl = base + 24576;
    const uint32_t aGNh = base + 32768,  aGNl = base + 40960;
    const uint32_t bReh = base + 49152,  bRel = base + 65536;
    const uint32_t bImh = base + 81920,  bIml = base + 98304;

    const int tid  = threadIdx.x;
    const int lane = tid & 31;
    const int wid  = tid >> 5;

    const int b    = blockIdx.y;
    const int row0 = blockIdx.x * 64;
    const long long aoff = (long long)b * NV * NC + (long long)row0 * NC;
    gxh += aoff; gxl += aoff; gyh += aoff; gyl += aoff;

    const int wr  = wid & 3;
    const int wc  = wid >> 2;
    const int rw0 = wr * 16;
    const int cw0 = wc * 64;
    const int grp = lane >> 3;
    const int lr  = lane & 7;

    float br[8][4], bi[8][4];
#pragma unroll
    for (int ni = 0; ni < 8; ni++)
#pragma unroll
        for (int q = 0; q < 4; q++) { br[ni][q] = 0.f; bi[ni][q] = 0.f; }

    for (int k0 = 0; k0 < NC; k0 += 64) {
        __syncthreads();
        // B tiles (128 rows x 64 k): 4 groups
#pragma unroll
        for (int g = 0; g < 4; g++) {
            const int G   = tid + 256 * g;
            const int row = G >> 3;
            const int v8  = (G & 7) * 8;
            const uint32_t sw = SWZ((uint32_t)(row * 128 + v8 * 2));
            CP_ASYNC(bReh + sw, BReh + (long long)row * NC + k0 + v8);
            CP_ASYNC(bRel + sw, BRel + (long long)row * NC + k0 + v8);
            CP_ASYNC(bImh + sw, BImh + (long long)row * NC + k0 + v8);
            CP_ASYNC(bIml + sw, BIml + (long long)row * NC + k0 + v8);
        }
        // gx tiles (64 rows): 2 groups
#pragma unroll
        for (int g = 0; g < 2; g++) {
            const int G   = tid + 256 * g;
            const int row = G >> 3;
            const int v8  = (G & 7) * 8;
            const uint32_t sw = SWZ((uint32_t)(row * 128 + v8 * 2));
            CP_ASYNC(aGXh + sw, gxh + (long long)row * NC + k0 + v8);
            CP_ASYNC(aGXl + sw, gxl + (long long)row * NC + k0 + v8);
        }
        CP_COMMIT();
        // gy + negated copy (manual loads)
#pragma unroll
        for (int g = 0; g < 2; g++) {
            const int G   = tid + 256 * g;
            const int row = G >> 3;
            const int v8  = (G & 7) * 8;
            const uint32_t sw = SWZ((uint32_t)(row * 128 + v8 * 2));
            uint4 th = *reinterpret_cast<const uint4*>(gyh + (long long)row * NC + k0 + v8);
            uint4 tl = *reinterpret_cast<const uint4*>(gyl + (long long)row * NC + k0 + v8);
            *reinterpret_cast<uint4*>(smem + (aGYh - base) + sw) = th;
            *reinterpret_cast<uint4*>(smem + (aGYl - base) + sw) = tl;
            th.x ^= 0x80008000u; th.y ^= 0x80008000u; th.z ^= 0x80008000u; th.w ^= 0x80008000u;
            tl.x ^= 0x80008000u; tl.y ^= 0x80008000u; tl.z ^= 0x80008000u; tl.w ^= 0x80008000u;
            *reinterpret_cast<uint4*>(smem + (aGNh - base) + sw) = th;
            *reinterpret_cast<uint4*>(smem + (aGNl - base) + sw) = tl;
        }
        CP_WAIT0();
        __syncthreads();

#pragma unroll
        for (int ks = 0; ks < 64; ks += 16) {
            const int ar = rw0 + (grp & 1) * 8 + lr;
            const int ac = ks + (grp >> 1) * 8;
            const uint32_t offA = SWZ((uint32_t)(ar * 128 + ac * 2));
            uint32_t offB[4];
#pragma unroll
            for (int nb = 0; nb < 4; nb++) {
                const int brow = cw0 + nb * 16 + (grp >> 1) * 8 + lr;
                const int bc = ks + (grp & 1) * 8;
                offB[nb] = SWZ((uint32_t)(brow * 128 + bc * 2));
            }
            uint32_t fgxh[4], fgxl[4], fgyh[4], fgyl[4], fgnh[4], fgnl[4];
            ldm4(fgxh, aGXh + offA); ldm4(fgxl, aGXl + offA);
            ldm4(fgyh, aGYh + offA); ldm4(fgyl, aGYl + offA);
            ldm4(fgnh, aGNh + offA); ldm4(fgnl, aGNl + offA);

            uint32_t bfr[4][4];
            // Are hi: br += gxh+gxl, bi += gyh+gyl
#pragma unroll
            for (int nb = 0; nb < 4; nb++) ldm4(bfr[nb], bReh + offB[nb]);
#pragma unroll
            for (int ni = 0; ni < 8; ni++) {
                const uint32_t* bb = &bfr[ni >> 1][(ni & 1) * 2];
                mma16816(br[ni], fgxh, bb); mma16816(br[ni], fgxl, bb);
                mma16816(bi[ni], fgyh, bb); mma16816(bi[ni], fgyl, bb);
            }
            // Are lo: br += gxh, bi += gyh
#pragma unroll
            for (int nb = 0; nb < 4; nb++) ldm4(bfr[nb], bRel + offB[nb]);
#pragma unroll
            for (int ni = 0; ni < 8; ni++) {
                const uint32_t* bb = &bfr[ni >> 1][(ni & 1) * 2];
                mma16816(br[ni], fgxh, bb);
                mma16816(bi[ni], fgyh, bb);
            }
            // Aim hi: br += (-gy)h + (-gy)l, bi += gxh + gxl
#pragma unroll
            for (int nb = 0; nb < 4; nb++) ldm4(bfr[nb], bImh + offB[nb]);
#pragma unroll
            for (int ni = 0; ni < 8; ni++) {
                const uint32_t* bb = &bfr[ni >> 1][(ni & 1) * 2];
                mma16816(br[ni], fgnh, bb); mma16816(br[ni], fgnl, bb);
                mma16816(bi[ni], fgxh, bb); mma16816(bi[ni], fgxl, bb);
            }
            // Aim lo: br += (-gy)h, bi += gxh
#pragma unroll
            for (int nb = 0; nb < 4; nb++) ldm4(bfr[nb], bIml + offB[nb]);
#pragma unroll
            for (int ni = 0; ni < 8; ni++) {
                const uint32_t* bb = &bfr[ni >> 1][(ni & 1) * 2];
                mma16816(br[ni], fgnh, bb);
                mma16816(bi[ni], fgxh, bb);
            }
        }
    }

    // epilogue: gfeat = tanh(gx*br + gy*bi) -> f cols [256:384]
    const int orow  = lane >> 2;
    const int ocol2 = (lane & 3) * 2;
#pragma unroll
    for (int ni = 0; ni < 8; ni++) {
        const int c = cw0 + ni * 8 + ocol2;
#pragma unroll
        for (int h = 0; h < 2; h++) {
            const int rl = rw0 + orow + h * 8;
            uint32_t xh = *reinterpret_cast<const uint32_t*>(&gxh[(long long)rl * NC + c]);
            uint32_t xl = *reinterpret_cast<const uint32_t*>(&gxl[(long long)rl * NC + c]);
            uint32_t yh = *reinterpret_cast<const uint32_t*>(&gyh[(long long)rl * NC + c]);
            uint32_t yl = *reinterpret_cast<const uint32_t*>(&gyl[(long long)rl * NC + c]);
            float gx0 = __bfloat162float(__ushort_as_bfloat16((unsigned short)(xh & 0xFFFF)))
                      + __bfloat162float(__ushort_as_bfloat16((unsigned short)(xl & 0xFFFF)));
            float gx1 = __bfloat162float(__ushort_as_bfloat16((unsigned short)(xh >> 16)))
                      + __bfloat162float(__ushort_as_bfloat16((unsigned short)(xl >> 16)));
            float gy0 = __bfloat162float(__ushort_as_bfloat16((unsigned short)(yh & 0xFFFF)))
                      + __bfloat162float(__ushort_as_bfloat16((unsigned short)(yl & 0xFFFF)));
            float gy1 = __bfloat162float(__ushort_as_bfloat16((unsigned short)(yh >> 16)))
                      + __bfloat162float(__ushort_as_bfloat16((unsigned short)(yl >> 16)));
            float o0 = tanhf(gx0 * br[ni][h * 2]     + gy0 * bi[ni][h * 2]);
            float o1 = tanhf(gx1 * br[ni][h * 2 + 1] + gy1 * bi[ni][h * 2 + 1]);
            *reinterpret_cast<float2*>(
                &f[((long long)b * NV + row0 + rl) * NMLP + 256 + c]) = make_float2(o0, o1);
        }
    }
}

// ---------------------------------------------------------------------------
// Small fp32 GEMM (only the x_in @ Wf feature GEMM, K=16)
// ---------------------------------------------------------------------------
__global__ __launch_bounds__(256) void gemm_n128(
    const float* __restrict__ A, int ldA,
    const float* __restrict__ W,
    const float* __restrict__ bias,
    float* __restrict__ C, int ldC,
    int Kd)
{
    __shared__ float As[16][68];
    __shared__ float Ws[16][128];

    const int row0 = blockIdx.x * 64;
    const int tid  = threadIdx.x;
    const int am  = tid >> 2;
    const int ak4 = (tid & 3) * 4;
    const int tx  = tid & 31;
    const int ty  = tid >> 5;
    const int c0  = tx * 4;
    const int r0  = ty * 8;

    float acc[8][4];
#pragma unroll
    for (int i = 0; i < 8; i++)
#pragma unroll
        for (int j = 0; j < 4; j++) acc[i][j] = 0.f;

    for (int k0 = 0; k0 < Kd; k0 += 16) {
        float4 av = *reinterpret_cast<const float4*>(
            &A[(long long)(row0 + am) * ldA + k0 + ak4]);
        const int i0 = tid * 2, i1 = i0 + 1;
        float4 wv0 = *reinterpret_cast<const float4*>(
            &W[(long long)(k0 + (i0 >> 5)) * 128 + (i0 & 31) * 4]);
        float4 wv1 = *reinterpret_cast<const float4*>(
            &W[(long long)(k0 + (i1 >> 5)) * 128 + (i1 & 31) * 4]);
        __syncthreads();
        As[ak4 + 0][am] = av.x; As[ak4 + 1][am] = av.y;
        As[ak4 + 2][am] = av.z; As[ak4 + 3][am] = av.w;
        *reinterpret_cast<float4*>(&Ws[i0 >> 5][(i0 & 31) * 4]) = wv0;
        *reinterpret_cast<float4*>(&Ws[i1 >> 5][(i1 & 31) * 4]) = wv1;
        __syncthreads();
#pragma unroll
        for (int kk = 0; kk < 16; kk++) {
            float4 w = *reinterpret_cast<const float4*>(&Ws[kk][c0]);
            float a[8];
#pragma unroll
            for (int i = 0; i < 8; i++) a[i] = As[kk][r0 + i];
#pragma unroll
            for (int i = 0; i < 8; i++) {
                acc[i][0] = fmaf(a[i], w.x, acc[i][0]);
                acc[i][1] = fmaf(a[i], w.y, acc[i][1]);
                acc[i][2] = fmaf(a[i], w.z, acc[i][2]);
                acc[i][3] = fmaf(a[i], w.w, acc[i][3]);
            }
        }
    }
    float4 bv = *reinterpret_cast<const float4*>(&bias[c0]);
#pragma unroll
    for (int i = 0; i < 8; i++) {
        long long off = (long long)(row0 + r0 + i) * ldC + c0;
        float4 r;
        r.x = acc[i][0] + bv.x; r.y = acc[i][1] + bv.y;
        r.z = acc[i][2] + bv.z; r.w = acc[i][3] + bv.w;
        *reinterpret_cast<float4*>(&C[off]) = r;
    }
}

// ---------------------------------------------------------------------------
// Spectral projection split-K stage 1 (NSLICE=64, 64 vertices per slice)
// ---------------------------------------------------------------------------
__global__ __launch_bounds__(256) void spec1(
    const float* __restrict__ evecs, const float* __restrict__ f,
    const float* __restrict__ mass, float* __restrict__ P)
{
    const int b  = blockIdx.y;
    const int sl = blockIdx.x;
    const int v0base = sl * (NV / NSLICE);   // 64 vertices per slice

    __shared__ float E[32][132], X[32][132];

    const float* ev = evecs + (long long)b * NV * NK;
    const float* xb = f + (long long)b * NV * NMLP;
    const float* mb = mass + b * NV;

    const int tid = threadIdx.x;
    const int vr = tid >> 3;
    const int cb = (tid & 7) * 16;
    const int r0 = (tid >> 4) * 8;
    const int c0 = (tid & 15) * 8;

    float acc[8][8];
#pragma unroll
    for (int i = 0; i < 8; i++)
#pragma unroll
        for (int j = 0; j < 8; j++) acc[i][j] = 0.f;

    for (int v0 = v0base; v0 < v0base + NV / NSLICE; v0 += 32) {
        const float* er = &ev[(long long)(v0 + vr) * NK + cb];
        const float* xr = &xb[(long long)(v0 + vr) * NMLP + cb];
        const float m = mb[v0 + vr];
        float4 e0 = *reinterpret_cast<const float4*>(er + 0);
        float4 e1 = *reinterpret_cast<const float4*>(er + 4);
        float4 e2 = *reinterpret_cast<const float4*>(er + 8);
        float4 e3 = *reinterpret_cast<const float4*>(er + 12);
        float4 x0 = *reinterpret_cast<const float4*>(xr + 0);
        float4 x1 = *reinterpret_cast<const float4*>(xr + 4);
        float4 x2 = *reinterpret_cast<const float4*>(xr + 8);
        float4 x3 = *reinterpret_cast<const float4*>(xr + 12);
        __syncthreads();
        *reinterpret_cast<float4*>(&E[vr][cb + 0])  = e0;
        *reinterpret_cast<float4*>(&E[vr][cb + 4])  = e1;
        *reinterpret_cast<float4*>(&E[vr][cb + 8])  = e2;
        *reinterpret_cast<float4*>(&E[vr][cb + 12]) = e3;
        x0.x *= m; x0.y *= m; x0.z *= m; x0.w *= m;
        x1.x *= m; x1.y *= m; x1.z *= m; x1.w *= m;
        x2.x *= m; x2.y *= m; x2.z *= m; x2.w *= m;
        x3.x *= m; x3.y *= m; x3.z *= m; x3.w *= m;
        *reinterpret_cast<float4*>(&X[vr][cb + 0])  = x0;
        *reinterpret_cast<float4*>(&X[vr][cb + 4])  = x1;
        *reinterpret_cast<float4*>(&X[vr][cb + 8])  = x2;
        *reinterpret_cast<float4*>(&X[vr][cb + 12]) = x3;
        __syncthreads();
#pragma unroll
        for (int v = 0; v < 32; v++) {
            float ka[8], xa[8];
            *reinterpret_cast<float4*>(ka)     = *reinterpret_cast<const float4*>(&E[v][r0]);
            *reinterpret_cast<float4*>(ka + 4) = *reinterpret_cast<const float4*>(&E[v][r0 + 4]);
            *reinterpret_cast<float4*>(xa)     = *reinterpret_cast<const float4*>(&X[v][c0]);
            *reinterpret_cast<float4*>(xa + 4) = *reinterpret_cast<const float4*>(&X[v][c0 + 4]);
#pragma unroll
            for (int i = 0; i < 8; i++)
#pragma unroll
                for (int j = 0; j < 8; j++)
                    acc[i][j] = fmaf(ka[i], xa[j], acc[i][j]);
        }
    }
#pragma unroll
    for (int i = 0; i < 8; i++) {
        float* pr = &P[(((long long)b * NSLICE + sl) * NK + r0 + i) * NC + c0];
        *reinterpret_cast<float4*>(pr)     = make_float4(acc[i][0], acc[i][1], acc[i][2], acc[i][3]);
        *reinterpret_cast<float4*>(pr + 4) = make_float4(acc[i][4], acc[i][5], acc[i][6], acc[i][7]);
    }
}

// ---------------------------------------------------------------------------
// Spectral stage 2 + transpose + split:
//   sT[b][c][k] (bf16 hi/lo) = exp(-evals[b,k]*max(t_i[c],1e-8)) * sum_sl P
// grid (NK/32, NC/32, NB), block (32,8)
// ---------------------------------------------------------------------------
__global__ void spec2t(const float* __restrict__ P, const float* __restrict__ evals,
                       const float* __restrict__ t_i,
                       __nv_bfloat16* __restrict__ sTh, __nv_bfloat16* __restrict__ sTl)
{
    __shared__ float tile[32][33];
    const int b  = blockIdx.z;
    const int k0 = blockIdx.x * 32;
    const int c0 = blockIdx.y * 32;
    const int tx = threadIdx.x, ty = threadIdx.y;
#pragma unroll
    for (int j = 0; j < 32; j += 8) {
        const int k = k0 + ty + j;
        float acc = 0.f;
        for (int sl = 0; sl < NSLICE; sl++)
            acc += P[(((long long)b * NSLICE + sl) * NK + k) * NC + c0 + tx];
        const float ti = fmaxf(t_i[c0 + tx], 1e-8f);
        tile[ty + j][tx] = expf(-evals[b * NK + k] * ti) * acc;
    }
    __syncthreads();
#pragma unroll
    for (int j = 0; j < 32; j += 8) {
        float x = tile[tx][ty + j];     // (k = k0+tx, c = c0+ty+j)
        __nv_bfloat16 h = __float2bfloat16(x);
        __nv_bfloat16 l = __float2bfloat16(x - __bfloat162float(h));
        long long o = ((long long)b * NC + c0 + ty + j) * NK + k0 + tx;
        sTh[o] = h; sTl[o] = l;
    }
}

// ---------------------------------------------------------------------------
extern "C" void kernel_launch(void* const* d_in, const int* in_sizes, int n_in,
                              void* d_out, int out_size)
{
    const float* x_in  = (const float*)d_in[0];
    const float* mass  = (const float*)d_in[1];
    const float* evals = (const float*)d_in[2];
    const float* evecs = (const float*)d_in[3];
    const float* gradX = (const float*)d_in[4];
    const float* gradY = (const float*)d_in[5];
    const float* Wf    = (const float*)d_in[6];
    const float* bf    = (const float*)d_in[7];
    const float* Wl    = (const float*)d_in[8];
    const float* bl    = (const float*)d_in[9];
    const float* t     = (const float*)d_in[10];
    const float* Are   = (const float*)d_in[11];
    const float* Aim   = (const float*)d_in[12];
    const float* W0    = (const float*)d_in[13];
    const float* b0    = (const float*)d_in[14];
    const float* W1    = (const float*)d_in[15];
    const float* b1    = (const float*)d_in[16];
    const float* W2    = (const float*)d_in[17];
    const float* b2    = (const float*)d_in[18];
    float* out = (float*)d_out;

    float *f, *P;
    __nv_bfloat16 *evTh, *evTl, *evh, *evl, *GXEh, *GXEl, *GYEh, *GYEl;
    __nv_bfloat16 *sTh, *sTl, *gxh, *gxl, *gyh, *gyl, *h0h, *h0l, *h1h, *h1l;
    __nv_bfloat16 *W0Th, *W0Tl, *W1Th, *W1Tl, *W2Th, *W2Tl;
    __nv_bfloat16 *AreTh, *AreTl, *AimTh, *AimTl, *WlTh, *WlTl;
    cudaGetSymbolAddress((void**)&f,     g_f);
    cudaGetSymbolAddress((void**)&P,     g_P);
    cudaGetSymbolAddress((void**)&evTh,  g_evTh);
    cudaGetSymbolAddress((void**)&evTl,  g_evTl);
    cudaGetSymbolAddress((void**)&evh,   g_evh);
    cudaGetSymbolAddress((void**)&evl,   g_evl);
    cudaGetSymbolAddress((void**)&GXEh,  g_GXEh);
    cudaGetSymbolAddress((void**)&GXEl,  g_GXEl);
    cudaGetSymbolAddress((void**)&GYEh,  g_GYEh);
    cudaGetSymbolAddress((void**)&GYEl,  g_GYEl);
    cudaGetSymbolAddress((void**)&sTh,   g_sTh);
    cudaGetSymbolAddress((void**)&sTl,   g_sTl);
    cudaGetSymbolAddress((void**)&gxh,   g_gxh);
    cudaGetSymbolAddress((void**)&gxl,   g_gxl);
    cudaGetSymbolAddress((void**)&gyh,   g_gyh);
    cudaGetSymbolAddress((void**)&gyl,   g_gyl);
    cudaGetSymbolAddress((void**)&h0h,   g_h0h);
    cudaGetSymbolAddress((void**)&h0l,   g_h0l);
    cudaGetSymbolAddress((void**)&h1h,   g_h1h);
    cudaGetSymbolAddress((void**)&h1l,   g_h1l);
    cudaGetSymbolAddress((void**)&W0Th,  g_W0Th);
    cudaGetSymbolAddress((void**)&W0Tl,  g_W0Tl);
    cudaGetSymbolAddress((void**)&W1Th,  g_W1Th);
    cudaGetSymbolAddress((void**)&W1Tl,  g_W1Tl);
    cudaGetSymbolAddress((void**)&W2Th,  g_W2Th);
    cudaGetSymbolAddress((void**)&W2Tl,  g_W2Tl);
    cudaGetSymbolAddress((void**)&AreTh, g_AreTh);
    cudaGetSymbolAddress((void**)&AreTl, g_AreTl);
    cudaGetSymbolAddress((void**)&AimTh, g_AimTh);
    cudaGetSymbolAddress((void**)&AimTl, g_AimTl);
    cudaGetSymbolAddress((void**)&WlTh,  g_WlTh);
    cudaGetSymbolAddress((void**)&WlTl,  g_WlTl);

    cudaFuncSetAttribute(mm_mma, cudaFuncAttributeMaxDynamicSharedMemorySize, SM_MM_TOTAL);
    cudaFuncSetAttribute(gemm_mma, cudaFuncAttributeMaxDynamicSharedMemorySize, SM_MM_TOTAL);
    cudaFuncSetAttribute(complex_mma, cudaFuncAttributeMaxDynamicSharedMemorySize, SM_CX);

    const long long sVK = (long long)NV * NK;
    const long long sVC = (long long)NV * NC;
    const long long sVM = (long long)NV * NMLP;
    const long long sCK = (long long)NC * NK;

    // x = x_in @ Wf + bf  -> f[:, 0:128]
    gemm_n128<<<dim3(NB * NV / 64), 256>>>(x_in, NCIN, Wf, bf, f, NMLP, NCIN);

    // one-time splits
    ev_split<<<dim3(NV / 32, NK / 32, NB), dim3(32, 8)>>>(evecs, evTh, evTl, evh, evl);
    w_split<<<dim3(NMLP / 32, 4, NBLK), dim3(32, 8)>>>(W0, W0Th, W0Tl, NMLP);
    w_split<<<dim3(NC / 32, 4, NBLK), dim3(32, 8)>>>(W1, W1Th, W1Tl, NC);
    w_split<<<dim3(NC / 32, 4, NBLK), dim3(32, 8)>>>(W2, W2Th, W2Tl, NC);
    w_split<<<dim3(NC / 32, 4, NBLK), dim3(32, 8)>>>(Are, AreTh, AreTl, NC);
    w_split<<<dim3(NC / 32, 4, NBLK), dim3(32, 8)>>>(Aim, AimTh, AimTl, NC);
    w_split<<<dim3(NC / 32, 4, 1), dim3(32, 8)>>>(Wl, WlTh, WlTl, NC);

    // GXE/GYE = gradX/gradY @ evecs (tensor cores, pre-split output)
    mm_mma<<<dim3(NV / 128, NB, 2), 256, SM_MM_TOTAL>>>(
        gradX, gradY, evTh, evTl, GXEh, GXEl, GYEh, GYEl);

    for (int i = 0; i < NBLK; i++) {
        const long long wo1 = (long long)i * NC * NC;
        const long long wo0 = (long long)i * NC * NMLP;
        // s^T = exp(-evals*t_i) * (evecs^T @ (x*mass)), split-K
        spec1<<<dim3(NSLICE, NB), 256>>>(evecs, f, mass, P);
        spec2t<<<dim3(NK / 32, NC / 32, NB), dim3(32, 8)>>>(P, evals, t + i * NC, sTh, sTl);
        // x_diff = evecs @ s -> f[:, 128:256] (fp32)
        gemm_mma<<<dim3(NV / 128, NB), 256, SM_MM_TOTAL>>>(
            evh, evl, NK, sVK, sTh, sTl, sCK, nullptr,
            f + NC, nullptr, NMLP, sVM, NK, F_ASPLIT);
        // gx = GXE @ s (split out), gy = GYE @ s (split out)
        gemm_mma<<<dim3(NV / 128, NB), 256, SM_MM_TOTAL>>>(
            GXEh, GXEl, NK, sVK, sTh, sTl, sCK, nullptr,
            gxh, gxl, NC, sVC, NK, F_ASPLIT | F_OSPLIT);
        gemm_mma<<<dim3(NV / 128, NB), 256, SM_MM_TOTAL>>>(
            GYEh, GYEl, NK, sVK, sTh, sTl, sCK, nullptr,
            gyh, gyl, NC, sVC, NK, F_ASPLIT | F_OSPLIT);
        // gfeat -> f[:, 256:384]
        complex_mma<<<dim3(NV / 64, NB), 256, SM_CX>>>(
            gxh, gxl, gyh, gyl,
            AreTh + wo1, AreTl + wo1, AimTh + wo1, AimTl + wo1, f);
        // MLP
        gemm_mma<<<dim3(NB * NV / 128, 1), 256, SM_MM_TOTAL>>>(
            f, nullptr, NMLP, 0, W0Th + wo0, W0Tl + wo0, 0, b0 + i * NC,
            h0h, h0l, NC, 0, NMLP, F_RELU | F_OSPLIT);
        gemm_mma<<<dim3(NB * NV / 128, 1), 256, SM_MM_TOTAL>>>(
            h0h, h0l, NC, 0, W1Th + wo1, W1Tl + wo1, 0, b1 + i * NC,
            h1h, h1l, NC, 0, NC, F_ASPLIT | F_RELU | F_OSPLIT);
        // x += h1 @ W2 + b2 (beta into f[:, 0:128])
        gemm_mma<<<dim3(NB * NV / 128, 1), 256, SM_MM_TOTAL>>>(
            h1h, h1l, NC, 0, W2Th + wo1, W2Tl + wo1, 0, b2 + i * NC,
            f, nullptr, NMLP, 0, NC, F_ASPLIT | F_BETA);
    }

    // out = x @ Wl + bl
    gemm_mma<<<dim3(NB * NV / 128, 1), 256, SM_MM_TOTAL>>>(
        f, nullptr, NMLP, 0, WlTh, WlTl, 0, bl,
        out, nullptr, NC, 0, NC, 0);
}